// round 1
// baseline (speedup 1.0000x reference)
#include <cuda_runtime.h>

#define NSEQ 2048
#define DDIM 64
#define NH 8
#define NB 8
#define HD 512      // NH * DDIM
#define INDIM 256

// Scratch (allocation-free: __device__ globals)
__device__ float g_Q[NB * NH * NSEQ * DDIM];   // [b][h][n][d], pre-scaled by 1/sqrt(D)
__device__ float g_K[NB * NH * NSEQ * DDIM];
__device__ float g_V[NB * NH * NSEQ * DDIM];
__device__ float g_ctx[NB * NSEQ * HD];        // [b][n][h*D+d]

// ---------------------------------------------------------------------------
// Kernel 1: QKV projection.  msg[16384,256] @ W[256,512] + bias
// grid (256, 8, 3), block 256.  BM=BN=64, BK=32, 4x4 microtile per thread.
// z selects (Wq,bq,g_Q) / (Wk,bk,g_K) / (Wv,bv,g_V).  Q gets *0.125 fold.
// ---------------------------------------------------------------------------
__global__ __launch_bounds__(256, 2)
void qkv_kernel(const float* __restrict__ msg,
                const float* __restrict__ Wq, const float* __restrict__ bq,
                const float* __restrict__ Wk, const float* __restrict__ bk,
                const float* __restrict__ Wv, const float* __restrict__ bv)
{
    __shared__ float As[64][33];
    __shared__ float Bs[32][65];

    const int z = blockIdx.z;
    const float* __restrict__ W    = (z == 0) ? Wq : (z == 1) ? Wk : Wv;
    const float* __restrict__ bias = (z == 0) ? bq : (z == 1) ? bk : bv;
    float* __restrict__ out        = (z == 0) ? g_Q : (z == 1) ? g_K : g_V;

    const int tid = threadIdx.x;
    const int tx = tid & 15;       // column lane (interleaved: c = j*16 + tx)
    const int ty = tid >> 4;       // row group: rows ty*4 .. ty*4+3
    const int m0 = blockIdx.x * 64;
    const int c0 = blockIdx.y * 64;

    float acc[4][4] = {};

    for (int k0 = 0; k0 < INDIM; k0 += 32) {
        // A tile 64x32 (512 float4)
        for (int f = tid; f < 512; f += 256) {
            int r = f >> 3, c4 = (f & 7) << 2;
            float4 v = *(const float4*)(msg + (size_t)(m0 + r) * INDIM + k0 + c4);
            As[r][c4 + 0] = v.x; As[r][c4 + 1] = v.y;
            As[r][c4 + 2] = v.z; As[r][c4 + 3] = v.w;
        }
        // B tile 32x64 (512 float4)
        for (int f = tid; f < 512; f += 256) {
            int r = f >> 4, c4 = (f & 15) << 2;
            float4 v = *(const float4*)(W + (size_t)(k0 + r) * HD + c0 + c4);
            Bs[r][c4 + 0] = v.x; Bs[r][c4 + 1] = v.y;
            Bs[r][c4 + 2] = v.z; Bs[r][c4 + 3] = v.w;
        }
        __syncthreads();
        #pragma unroll 8
        for (int kk = 0; kk < 32; kk++) {
            float a[4], b[4];
            #pragma unroll
            for (int i = 0; i < 4; i++) a[i] = As[ty * 4 + i][kk];
            #pragma unroll
            for (int j = 0; j < 4; j++) b[j] = Bs[kk][j * 16 + tx];
            #pragma unroll
            for (int i = 0; i < 4; i++)
                #pragma unroll
                for (int j = 0; j < 4; j++)
                    acc[i][j] += a[i] * b[j];
        }
        __syncthreads();
    }

    const float qscale = (z == 0) ? 0.125f : 1.0f;   // 1/sqrt(64) folded into Q
    #pragma unroll
    for (int i = 0; i < 4; i++) {
        int m = m0 + ty * 4 + i;
        int bb = m >> 11, n = m & (NSEQ - 1);
        #pragma unroll
        for (int j = 0; j < 4; j++) {
            int c = c0 + j * 16 + tx;
            float v = (acc[i][j] + bias[c]) * qscale;
            int h = c >> 6, d = c & 63;
            out[(((size_t)(bb * NH + h)) * NSEQ + n) * DDIM + d] = v;
        }
    }
}

// ---------------------------------------------------------------------------
// Kernel 2: flash attention with exclude-self mask.
// grid (B*H=64, N/64=32), block 128 (ty=tid>>3 in 0..15 rows*4, tx=tid&7).
// Thread owns S rows ty*4..+3, interleaved cols c = j*8+tx (j=0..7).
// Q,K stored d-major (transposed) in smem -> conflict-free reads unpadded.
// P never hits smem: O = P@V sources P via __shfl within 8-lane groups.
// Static smem = 3 * 64*64*4 = 49152 B (exactly 48KB).
// ---------------------------------------------------------------------------
__global__ __launch_bounds__(128, 4)
void attn_kernel()
{
    __shared__ float Qst[DDIM][64];   // [d][q]
    __shared__ float Kst[DDIM][64];   // [d][c]
    __shared__ float Vs[64][DDIM];    // [key][d]

    const int bh = blockIdx.x;          // b*8 + h
    const int q0 = blockIdx.y * 64;
    const int tid = threadIdx.x;
    const int tx = tid & 7;
    const int ty = tid >> 3;

    const float* __restrict__ Qg = g_Q + (size_t)bh * NSEQ * DDIM;
    const float* __restrict__ Kg = g_K + (size_t)bh * NSEQ * DDIM;
    const float* __restrict__ Vg = g_V + (size_t)bh * NSEQ * DDIM;

    // Load Q tile transposed: r-fast mapping (conflict-free STS)
    for (int f = tid; f < 1024; f += 128) {
        int r = f & 63, c4 = (f >> 6) << 2;
        float4 v = *(const float4*)(Qg + (size_t)(q0 + r) * DDIM + c4);
        Qst[c4 + 0][r] = v.x; Qst[c4 + 1][r] = v.y;
        Qst[c4 + 2][r] = v.z; Qst[c4 + 3][r] = v.w;
    }

    float mrow[4], lrow[4], O[4][8];
    #pragma unroll
    for (int i = 0; i < 4; i++) {
        mrow[i] = -3.0e38f;
        lrow[i] = 0.0f;
        #pragma unroll
        for (int j = 0; j < 8; j++) O[i][j] = 0.0f;
    }

    for (int kt = 0; kt < NSEQ / 64; kt++) {
        const int k0 = kt * 64;
        __syncthreads();   // Q ready (iter 0) / previous O-phase done with Vs

        // K tile transposed
        for (int f = tid; f < 1024; f += 128) {
            int r = f & 63, c4 = (f >> 6) << 2;
            float4 v = *(const float4*)(Kg + (size_t)(k0 + r) * DDIM + c4);
            Kst[c4 + 0][r] = v.x; Kst[c4 + 1][r] = v.y;
            Kst[c4 + 2][r] = v.z; Kst[c4 + 3][r] = v.w;
        }
        // V tile row-major
        for (int f = tid; f < 1024; f += 128) {
            int r = f >> 4, c4 = (f & 15) << 2;
            float4 v = *(const float4*)(Vg + (size_t)(k0 + r) * DDIM + c4);
            Vs[r][c4 + 0] = v.x; Vs[r][c4 + 1] = v.y;
            Vs[r][c4 + 2] = v.z; Vs[r][c4 + 3] = v.w;
        }
        __syncthreads();

        // ---- S = Q @ K^T (already scaled) ----
        float acc[4][8] = {};
        #pragma unroll 16
        for (int d = 0; d < 64; d++) {
            float4 av = *(const float4*)(&Qst[d][ty * 4]);
            float a[4] = {av.x, av.y, av.z, av.w};
            float b[8];
            #pragma unroll
            for (int j = 0; j < 8; j++) b[j] = Kst[d][j * 8 + tx];
            #pragma unroll
            for (int i = 0; i < 4; i++)
                #pragma unroll
                for (int j = 0; j < 8; j++)
                    acc[i][j] += a[i] * b[j];
        }

        // ---- exclude-self mask (scores already scaled; -1e9 matches ref) ----
        #pragma unroll
        for (int i = 0; i < 4; i++) {
            int qg = q0 + ty * 4 + i;
            #pragma unroll
            for (int j = 0; j < 8; j++)
                if (qg == k0 + j * 8 + tx) acc[i][j] = -1.0e9f;
        }

        // ---- online softmax (row reductions across the 8-lane tx group) ----
        #pragma unroll
        for (int i = 0; i < 4; i++) {
            float mt = acc[i][0];
            #pragma unroll
            for (int j = 1; j < 8; j++) mt = fmaxf(mt, acc[i][j]);
            mt = fmaxf(mt, __shfl_xor_sync(0xffffffffu, mt, 1));
            mt = fmaxf(mt, __shfl_xor_sync(0xffffffffu, mt, 2));
            mt = fmaxf(mt, __shfl_xor_sync(0xffffffffu, mt, 4));
            float mn = fmaxf(mrow[i], mt);
            float corr = __expf(mrow[i] - mn);
            mrow[i] = mn;
            float rs = 0.0f;
            #pragma unroll
            for (int j = 0; j < 8; j++) {
                float p = __expf(acc[i][j] - mn);
                acc[i][j] = p;
                rs += p;
            }
            rs += __shfl_xor_sync(0xffffffffu, rs, 1);
            rs += __shfl_xor_sync(0xffffffffu, rs, 2);
            rs += __shfl_xor_sync(0xffffffffu, rs, 4);
            lrow[i] = lrow[i] * corr + rs;
            #pragma unroll
            for (int j = 0; j < 8; j++) O[i][j] *= corr;
        }

        // ---- O += P @ V ; P sourced from registers via shfl (8-lane groups) ----
        #pragma unroll
        for (int jj = 0; jj < 8; jj++) {
            #pragma unroll
            for (int t = 0; t < 8; t++) {
                const int kk = jj * 8 + t;
                float a[4];
                #pragma unroll
                for (int i = 0; i < 4; i++)
                    a[i] = __shfl_sync(0xffffffffu, acc[i][jj], t, 8);
                float b[8];
                #pragma unroll
                for (int j = 0; j < 8; j++) b[j] = Vs[kk][j * 8 + tx];
                #pragma unroll
                for (int i = 0; i < 4; i++)
                    #pragma unroll
                    for (int j = 0; j < 8; j++)
                        O[i][j] += a[i] * b[j];
            }
        }
    }

    // ---- write ctx[b][n][h*64 + d] ----
    const int bb = bh >> 3, h = bh & 7;
    #pragma unroll
    for (int i = 0; i < 4; i++) {
        float inv = 1.0f / lrow[i];
        int n = q0 + ty * 4 + i;
        float* dst = g_ctx + ((size_t)bb * NSEQ + n) * HD + h * DDIM;
        #pragma unroll
        for (int j = 0; j < 8; j++)
            dst[j * 8 + tx] = O[i][j] * inv;
    }
}

// ---------------------------------------------------------------------------
// Kernel 3: out = ctx[16384,512] @ Wo[512,64]
// grid (256), block 256.  BM=64, BN=64 (full), BK=32, 4x4 microtile.
// ---------------------------------------------------------------------------
__global__ __launch_bounds__(256, 2)
void proj_kernel(const float* __restrict__ Wo, float* __restrict__ out)
{
    __shared__ float As[64][33];
    __shared__ float Bs[32][65];

    const int tid = threadIdx.x;
    const int tx = tid & 15;
    const int ty = tid >> 4;
    const int m0 = blockIdx.x * 64;

    float acc[4][4] = {};

    for (int k0 = 0; k0 < HD; k0 += 32) {
        for (int f = tid; f < 512; f += 256) {
            int r = f >> 3, c4 = (f & 7) << 2;
            float4 v = *(const float4*)(g_ctx + (size_t)(m0 + r) * HD + k0 + c4);
            As[r][c4 + 0] = v.x; As[r][c4 + 1] = v.y;
            As[r][c4 + 2] = v.z; As[r][c4 + 3] = v.w;
        }
        for (int f = tid; f < 512; f += 256) {
            int r = f >> 4, c4 = (f & 15) << 2;
            float4 v = *(const float4*)(Wo + (size_t)(k0 + r) * DDIM + c4);
            Bs[r][c4 + 0] = v.x; Bs[r][c4 + 1] = v.y;
            Bs[r][c4 + 2] = v.z; Bs[r][c4 + 3] = v.w;
        }
        __syncthreads();
        #pragma unroll 8
        for (int kk = 0; kk < 32; kk++) {
            float a[4], b[4];
            #pragma unroll
            for (int i = 0; i < 4; i++) a[i] = As[ty * 4 + i][kk];
            #pragma unroll
            for (int j = 0; j < 4; j++) b[j] = Bs[kk][j * 16 + tx];
            #pragma unroll
            for (int i = 0; i < 4; i++)
                #pragma unroll
                for (int j = 0; j < 4; j++)
                    acc[i][j] += a[i] * b[j];
        }
        __syncthreads();
    }

    #pragma unroll
    for (int i = 0; i < 4; i++) {
        int m = m0 + ty * 4 + i;
        #pragma unroll
        for (int j = 0; j < 4; j++)
            out[(size_t)m * DDIM + j * 16 + tx] = acc[i][j];
    }
}

// ---------------------------------------------------------------------------
extern "C" void kernel_launch(void* const* d_in, const int* in_sizes, int n_in,
                              void* d_out, int out_size)
{
    const float* msg = (const float*)d_in[0];
    const float* Wq  = (const float*)d_in[1];
    const float* bq  = (const float*)d_in[2];
    const float* Wk  = (const float*)d_in[3];
    const float* bk  = (const float*)d_in[4];
    const float* Wv  = (const float*)d_in[5];
    const float* bv  = (const float*)d_in[6];
    const float* Wo  = (const float*)d_in[7];
    float* out = (float*)d_out;

    qkv_kernel<<<dim3(256, 8, 3), 256>>>(msg, Wq, bq, Wk, bk, Wv, bv);
    attn_kernel<<<dim3(NB * NH, NSEQ / 64), 128>>>();
    proj_kernel<<<dim3(256, 1, 1), 256>>>(Wo, out);
}

// round 3
// speedup vs baseline: 2.3747x; 2.3747x over previous
#include <cuda_runtime.h>
#include <cuda_bf16.h>
#include <cstdint>

#define NSEQ 2048
#define DDIM 64
#define NH 8
#define NB 8
#define HD 512      // NH * DDIM
#define INDIM 256
#define BM 128      // queries per CTA (8 warps x 16 rows)
#define BN 64       // keys per tile
#define PADW 72     // padded bf16 row width (conflict-free: 4g+tig)

// ---------------- scratch (allocation-free __device__ globals) ----------------
__device__ __nv_bfloat16 g_Qh[NB * NH * NSEQ * DDIM];  // [b][h][n][d], pre-scaled 1/8
__device__ __nv_bfloat16 g_Ql[NB * NH * NSEQ * DDIM];
__device__ __nv_bfloat16 g_Kh[NB * NH * NSEQ * DDIM];
__device__ __nv_bfloat16 g_Kl[NB * NH * NSEQ * DDIM];
__device__ __nv_bfloat16 g_Vth[NB * NH * DDIM * NSEQ]; // transposed: [b][h][d][n]
__device__ __nv_bfloat16 g_Vtl[NB * NH * DDIM * NSEQ];
__device__ float g_ctx[NB * NSEQ * HD];                // [b][n][h*64+d]

// ---------------- mma.sync helpers (baseline PTX, compiles for sm_103) -------
__device__ __forceinline__ void mma16816(float* d, const uint32_t* a, const uint32_t* b) {
    asm volatile(
        "mma.sync.aligned.m16n8k16.row.col.f32.bf16.bf16.f32 "
        "{%0,%1,%2,%3}, {%4,%5,%6,%7}, {%8,%9}, {%0,%1,%2,%3};"
        : "+f"(d[0]), "+f"(d[1]), "+f"(d[2]), "+f"(d[3])
        : "r"(a[0]), "r"(a[1]), "r"(a[2]), "r"(a[3]), "r"(b[0]), "r"(b[1]));
}
// pack two f32 into bf16x2: elem0 -> low half, elem1 -> high half
__device__ __forceinline__ uint32_t pack_bf16(float e0, float e1) {
    uint32_t r;
    asm("cvt.rn.bf16x2.f32 %0, %1, %2;" : "=r"(r) : "f"(e1), "f"(e0));
    return r;
}

// ---------------------------------------------------------------------------
// Kernel 1: QKV projection -> split-bf16 outputs (V transposed).
// ---------------------------------------------------------------------------
__global__ __launch_bounds__(256, 2)
void qkv_kernel(const float* __restrict__ msg,
                const float* __restrict__ Wq, const float* __restrict__ bq,
                const float* __restrict__ Wk, const float* __restrict__ bk,
                const float* __restrict__ Wv, const float* __restrict__ bv)
{
    __shared__ float As[64][33];
    __shared__ float Bs[32][65];

    const int z = blockIdx.z;
    const float* __restrict__ W    = (z == 0) ? Wq : (z == 1) ? Wk : Wv;
    const float* __restrict__ bias = (z == 0) ? bq : (z == 1) ? bk : bv;

    const int tid = threadIdx.x;
    const int tx = tid & 15;
    const int ty = tid >> 4;
    const int m0 = blockIdx.x * 64;
    const int c0 = blockIdx.y * 64;

    float acc[4][4] = {};

    for (int k0 = 0; k0 < INDIM; k0 += 32) {
        for (int f = tid; f < 512; f += 256) {
            int r = f >> 3, c4 = (f & 7) << 2;
            float4 v = *(const float4*)(msg + (size_t)(m0 + r) * INDIM + k0 + c4);
            As[r][c4 + 0] = v.x; As[r][c4 + 1] = v.y;
            As[r][c4 + 2] = v.z; As[r][c4 + 3] = v.w;
        }
        for (int f = tid; f < 512; f += 256) {
            int r = f >> 4, c4 = (f & 15) << 2;
            float4 v = *(const float4*)(W + (size_t)(k0 + r) * HD + c0 + c4);
            Bs[r][c4 + 0] = v.x; Bs[r][c4 + 1] = v.y;
            Bs[r][c4 + 2] = v.z; Bs[r][c4 + 3] = v.w;
        }
        __syncthreads();
        #pragma unroll 8
        for (int kk = 0; kk < 32; kk++) {
            float a[4], b[4];
            #pragma unroll
            for (int i = 0; i < 4; i++) a[i] = As[ty * 4 + i][kk];
            #pragma unroll
            for (int j = 0; j < 4; j++) b[j] = Bs[kk][j * 16 + tx];
            #pragma unroll
            for (int i = 0; i < 4; i++)
                #pragma unroll
                for (int j = 0; j < 4; j++)
                    acc[i][j] += a[i] * b[j];
        }
        __syncthreads();
    }

    const float qscale = (z == 0) ? 0.125f : 1.0f;
    #pragma unroll
    for (int i = 0; i < 4; i++) {
        int m = m0 + ty * 4 + i;
        int bb = m >> 11, n = m & (NSEQ - 1);
        #pragma unroll
        for (int j = 0; j < 4; j++) {
            int c = c0 + j * 16 + tx;
            float v = (acc[i][j] + bias[c]) * qscale;
            int h = c >> 6, d = c & 63;
            __nv_bfloat16 hi = __float2bfloat16_rn(v);
            __nv_bfloat16 lo = __float2bfloat16_rn(v - __bfloat162float(hi));
            size_t bhh = (size_t)(bb * NH + h);
            if (z == 0) {
                size_t idx = (bhh * NSEQ + n) * DDIM + d;
                g_Qh[idx] = hi; g_Ql[idx] = lo;
            } else if (z == 1) {
                size_t idx = (bhh * NSEQ + n) * DDIM + d;
                g_Kh[idx] = hi; g_Kl[idx] = lo;
            } else {
                size_t idx = (bhh * DDIM + d) * NSEQ + n;   // transposed
                g_Vth[idx] = hi; g_Vtl[idx] = lo;
            }
        }
    }
}

// ---------------------------------------------------------------------------
// Kernel 2: flash attention via mma.sync (split-bf16, 3 passes per GEMM).
// grid (B*H=64, N/BM=16), block 256 = 8 warps, warp owns 16 query rows.
// smem (dynamic, 73728 B): Qh,Ql [128][72]; Kh,Kl,Vth,Vtl [64][72].
// ---------------------------------------------------------------------------
#define OFF_QH 0
#define OFF_QL 9216
#define OFF_KH 18432
#define OFF_KL 23040
#define OFF_VH 27648
#define OFF_VL 32256
#define ATTN_SMEM_ELEMS 36864
#define ATTN_SMEM_BYTES (ATTN_SMEM_ELEMS * 2)

__global__ void __launch_bounds__(256, 2)
attn_kernel()
{
    extern __shared__ __nv_bfloat16 sm[];

    const int tid  = threadIdx.x;
    const int wid  = tid >> 5;
    const int lane = tid & 31;
    const int g    = lane >> 2;
    const int tig  = lane & 3;
    const int bh   = blockIdx.x;
    const int q0   = blockIdx.y * BM;

    const size_t hb = (size_t)bh * NSEQ * DDIM;
    const __nv_bfloat16* __restrict__ gqh = g_Qh + hb + (size_t)q0 * DDIM;
    const __nv_bfloat16* __restrict__ gql = g_Ql + hb + (size_t)q0 * DDIM;
    const __nv_bfloat16* __restrict__ gkh = g_Kh + hb;
    const __nv_bfloat16* __restrict__ gkl = g_Kl + hb;
    const __nv_bfloat16* __restrict__ gvh = g_Vth + hb;   // [d][n]
    const __nv_bfloat16* __restrict__ gvl = g_Vtl + hb;

    // ---- load Q tile (hi/lo): 128 rows x 64 bf16, 8 chunks of 16B per row ----
    for (int f = tid; f < 1024; f += 256) {
        int r = f >> 3, c = (f & 7) << 3;           // c in bf16 elems
        *(uint4*)&sm[OFF_QH + r * PADW + c] = *(const uint4*)(gqh + r * DDIM + c);
        *(uint4*)&sm[OFF_QL + r * PADW + c] = *(const uint4*)(gql + r * DDIM + c);
    }

    float oacc[8][4];
    #pragma unroll
    for (int j = 0; j < 8; j++)
        #pragma unroll
        for (int t = 0; t < 4; t++) oacc[j][t] = 0.0f;
    float m0r = -3.0e38f, m1r = -3.0e38f, l0 = 0.0f, l1 = 0.0f;

    const int r0 = q0 + wid * 16 + g;   // this lane's even row
    const int r1 = r0 + 8;              // odd row
    const int aoff = (wid * 16 + g) * PADW + 2 * tig;   // Q A-frag base (elems)

    for (int kt = 0; kt < NSEQ / BN; kt++) {
        const int k0 = kt * BN;
        __syncthreads();   // previous iteration done reading K/V (and Q on iter 0)

        // ---- load K/Vt tiles (hi/lo): 64 rows x 64 bf16 each ----
        for (int f = tid; f < 512; f += 256) {
            int r = f >> 3, c = (f & 7) << 3;
            *(uint4*)&sm[OFF_KH + r * PADW + c] = *(const uint4*)(gkh + (size_t)(k0 + r) * DDIM + c);
            *(uint4*)&sm[OFF_KL + r * PADW + c] = *(const uint4*)(gkl + (size_t)(k0 + r) * DDIM + c);
            *(uint4*)&sm[OFF_VH + r * PADW + c] = *(const uint4*)(gvh + (size_t)r * NSEQ + k0 + c);
            *(uint4*)&sm[OFF_VL + r * PADW + c] = *(const uint4*)(gvl + (size_t)r * NSEQ + k0 + c);
        }
        __syncthreads();

        // ---- S = Qh*Kh + Ql*Kh + Qh*Kl  (warp tile 16 x 64) ----
        float sacc[8][4];
        #pragma unroll
        for (int j = 0; j < 8; j++)
            #pragma unroll
            for (int t = 0; t < 4; t++) sacc[j][t] = 0.0f;

        #pragma unroll
        for (int kc = 0; kc < 4; kc++) {
            uint32_t aqh[4], aql[4];
            const int ab = aoff + kc * 16;
            aqh[0] = *(const uint32_t*)&sm[OFF_QH + ab];
            aqh[1] = *(const uint32_t*)&sm[OFF_QH + ab + 8 * PADW];
            aqh[2] = *(const uint32_t*)&sm[OFF_QH + ab + 8];
            aqh[3] = *(const uint32_t*)&sm[OFF_QH + ab + 8 * PADW + 8];
            aql[0] = *(const uint32_t*)&sm[OFF_QL + ab];
            aql[1] = *(const uint32_t*)&sm[OFF_QL + ab + 8 * PADW];
            aql[2] = *(const uint32_t*)&sm[OFF_QL + ab + 8];
            aql[3] = *(const uint32_t*)&sm[OFF_QL + ab + 8 * PADW + 8];
            #pragma unroll
            for (int j = 0; j < 8; j++) {
                const int bb = (j * 8 + g) * PADW + kc * 16 + 2 * tig;
                uint32_t bkh[2], bkl[2];
                bkh[0] = *(const uint32_t*)&sm[OFF_KH + bb];
                bkh[1] = *(const uint32_t*)&sm[OFF_KH + bb + 8];
                bkl[0] = *(const uint32_t*)&sm[OFF_KL + bb];
                bkl[1] = *(const uint32_t*)&sm[OFF_KL + bb + 8];
                mma16816(sacc[j], aqh, bkh);
                mma16816(sacc[j], aql, bkh);
                mma16816(sacc[j], aqh, bkl);
            }
        }

        // ---- exclude-self mask ----
        #pragma unroll
        for (int j = 0; j < 8; j++) {
            const int c0 = k0 + j * 8 + 2 * tig;
            if (c0 == r0)     sacc[j][0] = -1.0e9f;
            if (c0 + 1 == r0) sacc[j][1] = -1.0e9f;
            if (c0 == r1)     sacc[j][2] = -1.0e9f;
            if (c0 + 1 == r1) sacc[j][3] = -1.0e9f;
        }

        // ---- online softmax (two rows per lane; quad reduction) ----
        float mt0 = sacc[0][0], mt1 = sacc[0][2];
        #pragma unroll
        for (int j = 0; j < 8; j++) {
            mt0 = fmaxf(mt0, fmaxf(sacc[j][0], sacc[j][1]));
            mt1 = fmaxf(mt1, fmaxf(sacc[j][2], sacc[j][3]));
        }
        mt0 = fmaxf(mt0, __shfl_xor_sync(0xffffffffu, mt0, 1));
        mt0 = fmaxf(mt0, __shfl_xor_sync(0xffffffffu, mt0, 2));
        mt1 = fmaxf(mt1, __shfl_xor_sync(0xffffffffu, mt1, 1));
        mt1 = fmaxf(mt1, __shfl_xor_sync(0xffffffffu, mt1, 2));
        const float mn0 = fmaxf(m0r, mt0);
        const float mn1 = fmaxf(m1r, mt1);
        const float corr0 = __expf(m0r - mn0);
        const float corr1 = __expf(m1r - mn1);
        m0r = mn0; m1r = mn1;

        float rs0 = 0.0f, rs1 = 0.0f;
        #pragma unroll
        for (int j = 0; j < 8; j++) {
            sacc[j][0] = __expf(sacc[j][0] - mn0);
            sacc[j][1] = __expf(sacc[j][1] - mn0);
            sacc[j][2] = __expf(sacc[j][2] - mn1);
            sacc[j][3] = __expf(sacc[j][3] - mn1);
            rs0 += sacc[j][0] + sacc[j][1];
            rs1 += sacc[j][2] + sacc[j][3];
        }
        rs0 += __shfl_xor_sync(0xffffffffu, rs0, 1);
        rs0 += __shfl_xor_sync(0xffffffffu, rs0, 2);
        rs1 += __shfl_xor_sync(0xffffffffu, rs1, 1);
        rs1 += __shfl_xor_sync(0xffffffffu, rs1, 2);
        l0 = l0 * corr0 + rs0;
        l1 = l1 * corr1 + rs1;

        #pragma unroll
        for (int j = 0; j < 8; j++) {
            oacc[j][0] *= corr0; oacc[j][1] *= corr0;
            oacc[j][2] *= corr1; oacc[j][3] *= corr1;
        }

        // ---- O += P @ V : P split to bf16 hi/lo directly in registers ----
        #pragma unroll
        for (int kc = 0; kc < 4; kc++) {
            const int j0 = 2 * kc, j1 = 2 * kc + 1;
            uint32_t aph[4], apl[4];
            aph[0] = pack_bf16(sacc[j0][0], sacc[j0][1]);
            aph[1] = pack_bf16(sacc[j0][2], sacc[j0][3]);
            aph[2] = pack_bf16(sacc[j1][0], sacc[j1][1]);
            aph[3] = pack_bf16(sacc[j1][2], sacc[j1][3]);
            {
                float e0 = sacc[j0][0] - __uint_as_float(aph[0] << 16);
                float e1 = sacc[j0][1] - __uint_as_float(aph[0] & 0xffff0000u);
                float e2 = sacc[j0][2] - __uint_as_float(aph[1] << 16);
                float e3 = sacc[j0][3] - __uint_as_float(aph[1] & 0xffff0000u);
                apl[0] = pack_bf16(e0, e1);
                apl[1] = pack_bf16(e2, e3);
                e0 = sacc[j1][0] - __uint_as_float(aph[2] << 16);
                e1 = sacc[j1][1] - __uint_as_float(aph[2] & 0xffff0000u);
                e2 = sacc[j1][2] - __uint_as_float(aph[3] << 16);
                e3 = sacc[j1][3] - __uint_as_float(aph[3] & 0xffff0000u);
                apl[2] = pack_bf16(e0, e1);
                apl[3] = pack_bf16(e2, e3);
            }
            #pragma unroll
            for (int j = 0; j < 8; j++) {
                const int bb = (j * 8 + g) * PADW + kc * 16 + 2 * tig;
                uint32_t bvh[2], bvl[2];
                bvh[0] = *(const uint32_t*)&sm[OFF_VH + bb];
                bvh[1] = *(const uint32_t*)&sm[OFF_VH + bb + 8];
                bvl[0] = *(const uint32_t*)&sm[OFF_VL + bb];
                bvl[1] = *(const uint32_t*)&sm[OFF_VL + bb + 8];
                mma16816(oacc[j], aph, bvh);
                mma16816(oacc[j], apl, bvh);
                mma16816(oacc[j], aph, bvl);
            }
        }
    }

    // ---- epilogue: ctx[b][n][h*64+d] ----
    const int bb = bh >> 3, h = bh & 7;
    const float inv0 = 1.0f / l0;
    const float inv1 = 1.0f / l1;
    float* dst0 = g_ctx + ((size_t)bb * NSEQ + r0) * HD + h * DDIM;
    float* dst1 = g_ctx + ((size_t)bb * NSEQ + r1) * HD + h * DDIM;
    #pragma unroll
    for (int j = 0; j < 8; j++) {
        const int c = j * 8 + 2 * tig;
        *(float2*)(dst0 + c) = make_float2(oacc[j][0] * inv0, oacc[j][1] * inv0);
        *(float2*)(dst1 + c) = make_float2(oacc[j][2] * inv1, oacc[j][3] * inv1);
    }
}

// ---------------------------------------------------------------------------
// Kernel 3: out = ctx[16384,512] @ Wo[512,64]
// ---------------------------------------------------------------------------
__global__ __launch_bounds__(256, 2)
void proj_kernel(const float* __restrict__ Wo, float* __restrict__ out)
{
    __shared__ float As[64][33];
    __shared__ float Bs[32][65];

    const int tid = threadIdx.x;
    const int tx = tid & 15;
    const int ty = tid >> 4;
    const int m0 = blockIdx.x * 64;

    float acc[4][4] = {};

    for (int k0 = 0; k0 < HD; k0 += 32) {
        for (int f = tid; f < 512; f += 256) {
            int r = f >> 3, c4 = (f & 7) << 2;
            float4 v = *(const float4*)(g_ctx + (size_t)(m0 + r) * HD + k0 + c4);
            As[r][c4 + 0] = v.x; As[r][c4 + 1] = v.y;
            As[r][c4 + 2] = v.z; As[r][c4 + 3] = v.w;
        }
        for (int f = tid; f < 512; f += 256) {
            int r = f >> 4, c4 = (f & 15) << 2;
            float4 v = *(const float4*)(Wo + (size_t)(k0 + r) * DDIM + c4);
            Bs[r][c4 + 0] = v.x; Bs[r][c4 + 1] = v.y;
            Bs[r][c4 + 2] = v.z; Bs[r][c4 + 3] = v.w;
        }
        __syncthreads();
        #pragma unroll 8
        for (int kk = 0; kk < 32; kk++) {
            float a[4], b[4];
            #pragma unroll
            for (int i = 0; i < 4; i++) a[i] = As[ty * 4 + i][kk];
            #pragma unroll
            for (int j = 0; j < 4; j++) b[j] = Bs[kk][j * 16 + tx];
            #pragma unroll
            for (int i = 0; i < 4; i++)
                #pragma unroll
                for (int j = 0; j < 4; j++)
                    acc[i][j] += a[i] * b[j];
        }
        __syncthreads();
    }

    #pragma unroll
    for (int i = 0; i < 4; i++) {
        int mm = m0 + ty * 4 + i;
        #pragma unroll
        for (int j = 0; j < 4; j++)
            out[(size_t)mm * DDIM + j * 16 + tx] = acc[i][j];
    }
}

// ---------------------------------------------------------------------------
extern "C" void kernel_launch(void* const* d_in, const int* in_sizes, int n_in,
                              void* d_out, int out_size)
{
    const float* msg = (const float*)d_in[0];
    const float* Wq  = (const float*)d_in[1];
    const float* bq  = (const float*)d_in[2];
    const float* Wk  = (const float*)d_in[3];
    const float* bk  = (const float*)d_in[4];
    const float* Wv  = (const float*)d_in[5];
    const float* bv  = (const float*)d_in[6];
    const float* Wo  = (const float*)d_in[7];
    float* out = (float*)d_out;

    cudaFuncSetAttribute(attn_kernel, cudaFuncAttributeMaxDynamicSharedMemorySize,
                         ATTN_SMEM_BYTES);

    qkv_kernel<<<dim3(256, 8, 3), 256>>>(msg, Wq, bq, Wk, bk, Wv, bv);
    attn_kernel<<<dim3(NB * NH, NSEQ / BM), 256, ATTN_SMEM_BYTES>>>();
    proj_kernel<<<dim3(256, 1, 1), 256>>>(Wo, out);
}

// round 4
// speedup vs baseline: 3.1973x; 1.3464x over previous
#include <cuda_runtime.h>
#include <cuda_bf16.h>
#include <cstdint>

#define NSEQ 2048
#define DDIM 64
#define NH 8
#define NB 8
#define HD 512      // NH * DDIM
#define INDIM 256
#define BM 128      // queries per CTA (8 warps x 16 rows)
#define BN 64       // keys per tile
#define PADW 72     // padded bf16 row width (conflict-free)

// ---------------- scratch (allocation-free __device__ globals) ----------------
__device__ __nv_bfloat16 g_Mh[NB * NSEQ * INDIM];      // msg split
__device__ __nv_bfloat16 g_Ml[NB * NSEQ * INDIM];
__device__ __nv_bfloat16 g_Wth[3 * HD * INDIM];        // W^T per z: [z][n=512][k=256]
__device__ __nv_bfloat16 g_Wtl[3 * HD * INDIM];
__device__ __nv_bfloat16 g_Woth[DDIM * HD];            // Wo^T: [n=64][k=512]
__device__ __nv_bfloat16 g_Wotl[DDIM * HD];

__device__ __nv_bfloat16 g_Qh[NB * NH * NSEQ * DDIM];  // [b][h][n][d], pre-scaled 1/8
__device__ __nv_bfloat16 g_Ql[NB * NH * NSEQ * DDIM];
__device__ __nv_bfloat16 g_Kh[NB * NH * NSEQ * DDIM];
__device__ __nv_bfloat16 g_Kl[NB * NH * NSEQ * DDIM];
__device__ __nv_bfloat16 g_Vth[NB * NH * DDIM * NSEQ]; // transposed: [b][h][d][n]
__device__ __nv_bfloat16 g_Vtl[NB * NH * DDIM * NSEQ];
__device__ __nv_bfloat16 g_Ch[NB * NSEQ * HD];         // ctx split: [b][n][h*64+d]
__device__ __nv_bfloat16 g_Cl[NB * NSEQ * HD];

// ---------------- mma.sync helpers (baseline PTX, sm_103-safe) ----------------
__device__ __forceinline__ void mma16816(float* d, const uint32_t* a, const uint32_t* b) {
    asm volatile(
        "mma.sync.aligned.m16n8k16.row.col.f32.bf16.bf16.f32 "
        "{%0,%1,%2,%3}, {%4,%5,%6,%7}, {%8,%9}, {%0,%1,%2,%3};"
        : "+f"(d[0]), "+f"(d[1]), "+f"(d[2]), "+f"(d[3])
        : "r"(a[0]), "r"(a[1]), "r"(a[2]), "r"(a[3]), "r"(b[0]), "r"(b[1]));
}
// pack two f32 into bf16x2: elem0 -> low half, elem1 -> high half
__device__ __forceinline__ uint32_t pack_bf16(float e0, float e1) {
    uint32_t r;
    asm("cvt.rn.bf16x2.f32 %0, %1, %2;" : "=r"(r) : "f"(e1), "f"(e0));
    return r;
}
__device__ __forceinline__ void split2(float v0, float v1, uint32_t& hi, uint32_t& lo) {
    hi = pack_bf16(v0, v1);
    float r0 = v0 - __uint_as_float(hi << 16);
    float r1 = v1 - __uint_as_float(hi & 0xffff0000u);
    lo = pack_bf16(r0, r1);
}

// ---------------------------------------------------------------------------
// Kernel 0: fp32 -> split-bf16 conversions (msg, W^T x3, Wo^T)
// ---------------------------------------------------------------------------
__global__ void __launch_bounds__(256)
conv_kernel(const float* __restrict__ msg,
            const float* __restrict__ Wq, const float* __restrict__ Wk,
            const float* __restrict__ Wv, const float* __restrict__ Wo)
{
    const int stride = gridDim.x * blockDim.x;
    const int gid = blockIdx.x * blockDim.x + threadIdx.x;

    for (int i = gid; i < NB * NSEQ * INDIM; i += stride) {
        float v = msg[i];
        __nv_bfloat16 hi = __float2bfloat16_rn(v);
        g_Mh[i] = hi;
        g_Ml[i] = __float2bfloat16_rn(v - __bfloat162float(hi));
    }
    for (int i = gid; i < HD * INDIM; i += stride) {
        int n = i / INDIM, k = i % INDIM;
        #pragma unroll
        for (int z = 0; z < 3; z++) {
            const float* W = (z == 0) ? Wq : (z == 1) ? Wk : Wv;
            float v = W[(size_t)k * HD + n];
            __nv_bfloat16 hi = __float2bfloat16_rn(v);
            g_Wth[z * HD * INDIM + i] = hi;
            g_Wtl[z * HD * INDIM + i] = __float2bfloat16_rn(v - __bfloat162float(hi));
        }
    }
    for (int i = gid; i < DDIM * HD; i += stride) {
        int n = i / HD, k = i % HD;
        float v = Wo[(size_t)k * DDIM + n];
        __nv_bfloat16 hi = __float2bfloat16_rn(v);
        g_Woth[i] = hi;
        g_Wotl[i] = __float2bfloat16_rn(v - __bfloat162float(hi));
    }
}

// ---------------------------------------------------------------------------
// Kernel 1: QKV projection via mma.sync. CTA 128x128, warp 16x128, K=256.
// grid (M/128=128, 512/128=4, z=3), block 256.
// ---------------------------------------------------------------------------
#define QK_AH 0
#define QK_AL 9216
#define QK_BH 18432
#define QK_BL 27648
#define QK_SMEM_BYTES (36864 * 2)

__global__ void __launch_bounds__(256, 2)
qkv_kernel(const float* __restrict__ bq, const float* __restrict__ bk,
           const float* __restrict__ bv)
{
    extern __shared__ __nv_bfloat16 sm[];

    const int tid  = threadIdx.x;
    const int wid  = tid >> 5;
    const int lane = tid & 31;
    const int g    = lane >> 2;
    const int tig  = lane & 3;
    const int z    = blockIdx.z;
    const int m0   = blockIdx.x * 128;
    const int n0   = blockIdx.y * 128;

    const float* __restrict__ bias = (z == 0) ? bq : (z == 1) ? bk : bv;
    const __nv_bfloat16* __restrict__ gBh = g_Wth + (size_t)z * HD * INDIM;
    const __nv_bfloat16* __restrict__ gBl = g_Wtl + (size_t)z * HD * INDIM;

    float sacc[16][4];
    #pragma unroll
    for (int j = 0; j < 16; j++)
        #pragma unroll
        for (int t = 0; t < 4; t++) sacc[j][t] = 0.0f;

    const int aoff = (wid * 16 + g) * PADW + 2 * tig;

    for (int c0 = 0; c0 < 4; c0++) {
        const int k0 = c0 * 64;
        __syncthreads();
        for (int f = tid; f < 1024; f += 256) {
            int r = f >> 3, c = (f & 7) << 3;
            *(uint4*)&sm[QK_AH + r * PADW + c] = *(const uint4*)(g_Mh + (size_t)(m0 + r) * INDIM + k0 + c);
            *(uint4*)&sm[QK_AL + r * PADW + c] = *(const uint4*)(g_Ml + (size_t)(m0 + r) * INDIM + k0 + c);
            *(uint4*)&sm[QK_BH + r * PADW + c] = *(const uint4*)(gBh + (size_t)(n0 + r) * INDIM + k0 + c);
            *(uint4*)&sm[QK_BL + r * PADW + c] = *(const uint4*)(gBl + (size_t)(n0 + r) * INDIM + k0 + c);
        }
        __syncthreads();

        #pragma unroll
        for (int kc = 0; kc < 4; kc++) {
            uint32_t ah[4], al[4];
            const int ab = aoff + kc * 16;
            ah[0] = *(const uint32_t*)&sm[QK_AH + ab];
            ah[1] = *(const uint32_t*)&sm[QK_AH + ab + 8 * PADW];
            ah[2] = *(const uint32_t*)&sm[QK_AH + ab + 8];
            ah[3] = *(const uint32_t*)&sm[QK_AH + ab + 8 * PADW + 8];
            al[0] = *(const uint32_t*)&sm[QK_AL + ab];
            al[1] = *(const uint32_t*)&sm[QK_AL + ab + 8 * PADW];
            al[2] = *(const uint32_t*)&sm[QK_AL + ab + 8];
            al[3] = *(const uint32_t*)&sm[QK_AL + ab + 8 * PADW + 8];
            #pragma unroll
            for (int j = 0; j < 16; j++) {
                const int bb = (j * 8 + g) * PADW + kc * 16 + 2 * tig;
                uint32_t bh[2], bl[2];
                bh[0] = *(const uint32_t*)&sm[QK_BH + bb];
                bh[1] = *(const uint32_t*)&sm[QK_BH + bb + 8];
                bl[0] = *(const uint32_t*)&sm[QK_BL + bb];
                bl[1] = *(const uint32_t*)&sm[QK_BL + bb + 8];
                mma16816(sacc[j], ah, bh);
                mma16816(sacc[j], al, bh);
                mma16816(sacc[j], ah, bl);
            }
        }
    }

    // ---- epilogue: bias + qscale, split bf16, scatter to Q/K/Vt layouts ----
    const float qscale = (z == 0) ? 0.125f : 1.0f;
    const int r0 = m0 + wid * 16 + g;
    const int r1 = r0 + 8;
    const int bb0 = r0 >> 11, nn0 = r0 & (NSEQ - 1);
    const int bb1 = r1 >> 11, nn1 = r1 & (NSEQ - 1);

    #pragma unroll
    for (int j = 0; j < 16; j++) {
        const int cg = n0 + j * 8 + 2 * tig;      // even, pair inside one head
        const int h = cg >> 6, d = cg & 63;
        const float b0 = bias[cg], b1 = bias[cg + 1];
        float v00 = (sacc[j][0] + b0) * qscale, v01 = (sacc[j][1] + b1) * qscale;
        float v10 = (sacc[j][2] + b0) * qscale, v11 = (sacc[j][3] + b1) * qscale;
        uint32_t hi0, lo0, hi1, lo1;
        split2(v00, v01, hi0, lo0);
        split2(v10, v11, hi1, lo1);

        if (z == 2) {
            // Vt layout: [b][h][d][n]
            size_t base0 = ((size_t)(bb0 * NH + h) * DDIM + d) * NSEQ + nn0;
            size_t base1 = ((size_t)(bb1 * NH + h) * DDIM + d) * NSEQ + nn1;
            g_Vth[base0]        = __ushort_as_bfloat16((unsigned short)(hi0 & 0xffff));
            g_Vth[base0 + NSEQ] = __ushort_as_bfloat16((unsigned short)(hi0 >> 16));
            g_Vtl[base0]        = __ushort_as_bfloat16((unsigned short)(lo0 & 0xffff));
            g_Vtl[base0 + NSEQ] = __ushort_as_bfloat16((unsigned short)(lo0 >> 16));
            g_Vth[base1]        = __ushort_as_bfloat16((unsigned short)(hi1 & 0xffff));
            g_Vth[base1 + NSEQ] = __ushort_as_bfloat16((unsigned short)(hi1 >> 16));
            g_Vtl[base1]        = __ushort_as_bfloat16((unsigned short)(lo1 & 0xffff));
            g_Vtl[base1 + NSEQ] = __ushort_as_bfloat16((unsigned short)(lo1 >> 16));
        } else {
            __nv_bfloat16* dh = (z == 0) ? g_Qh : g_Kh;
            __nv_bfloat16* dl = (z == 0) ? g_Ql : g_Kl;
            size_t i0 = ((size_t)(bb0 * NH + h) * NSEQ + nn0) * DDIM + d;
            size_t i1 = ((size_t)(bb1 * NH + h) * NSEQ + nn1) * DDIM + d;
            *(uint32_t*)&dh[i0] = hi0; *(uint32_t*)&dl[i0] = lo0;
            *(uint32_t*)&dh[i1] = hi1; *(uint32_t*)&dl[i1] = lo1;
        }
    }
}

// ---------------------------------------------------------------------------
// Kernel 2: flash attention via mma.sync (split-bf16, 3 passes per GEMM).
// ---------------------------------------------------------------------------
#define OFF_QH 0
#define OFF_QL 9216
#define OFF_KH 18432
#define OFF_KL 23040
#define OFF_VH 27648
#define OFF_VL 32256
#define ATTN_SMEM_BYTES (36864 * 2)

__global__ void __launch_bounds__(256, 2)
attn_kernel()
{
    extern __shared__ __nv_bfloat16 sm[];

    const int tid  = threadIdx.x;
    const int wid  = tid >> 5;
    const int lane = tid & 31;
    const int g    = lane >> 2;
    const int tig  = lane & 3;
    const int bh   = blockIdx.x;
    const int q0   = blockIdx.y * BM;

    const size_t hb = (size_t)bh * NSEQ * DDIM;
    const __nv_bfloat16* __restrict__ gqh = g_Qh + hb + (size_t)q0 * DDIM;
    const __nv_bfloat16* __restrict__ gql = g_Ql + hb + (size_t)q0 * DDIM;
    const __nv_bfloat16* __restrict__ gkh = g_Kh + hb;
    const __nv_bfloat16* __restrict__ gkl = g_Kl + hb;
    const __nv_bfloat16* __restrict__ gvh = g_Vth + hb;   // [d][n]
    const __nv_bfloat16* __restrict__ gvl = g_Vtl + hb;

    for (int f = tid; f < 1024; f += 256) {
        int r = f >> 3, c = (f & 7) << 3;
        *(uint4*)&sm[OFF_QH + r * PADW + c] = *(const uint4*)(gqh + r * DDIM + c);
        *(uint4*)&sm[OFF_QL + r * PADW + c] = *(const uint4*)(gql + r * DDIM + c);
    }

    float oacc[8][4];
    #pragma unroll
    for (int j = 0; j < 8; j++)
        #pragma unroll
        for (int t = 0; t < 4; t++) oacc[j][t] = 0.0f;
    float m0r = -3.0e38f, m1r = -3.0e38f, l0 = 0.0f, l1 = 0.0f;

    const int r0 = q0 + wid * 16 + g;
    const int r1 = r0 + 8;
    const int aoff = (wid * 16 + g) * PADW + 2 * tig;

    for (int kt = 0; kt < NSEQ / BN; kt++) {
        const int k0 = kt * BN;
        __syncthreads();

        for (int f = tid; f < 512; f += 256) {
            int r = f >> 3, c = (f & 7) << 3;
            *(uint4*)&sm[OFF_KH + r * PADW + c] = *(const uint4*)(gkh + (size_t)(k0 + r) * DDIM + c);
            *(uint4*)&sm[OFF_KL + r * PADW + c] = *(const uint4*)(gkl + (size_t)(k0 + r) * DDIM + c);
            *(uint4*)&sm[OFF_VH + r * PADW + c] = *(const uint4*)(gvh + (size_t)r * NSEQ + k0 + c);
            *(uint4*)&sm[OFF_VL + r * PADW + c] = *(const uint4*)(gvl + (size_t)r * NSEQ + k0 + c);
        }
        __syncthreads();

        float sacc[8][4];
        #pragma unroll
        for (int j = 0; j < 8; j++)
            #pragma unroll
            for (int t = 0; t < 4; t++) sacc[j][t] = 0.0f;

        #pragma unroll
        for (int kc = 0; kc < 4; kc++) {
            uint32_t aqh[4], aql[4];
            const int ab = aoff + kc * 16;
            aqh[0] = *(const uint32_t*)&sm[OFF_QH + ab];
            aqh[1] = *(const uint32_t*)&sm[OFF_QH + ab + 8 * PADW];
            aqh[2] = *(const uint32_t*)&sm[OFF_QH + ab + 8];
            aqh[3] = *(const uint32_t*)&sm[OFF_QH + ab + 8 * PADW + 8];
            aql[0] = *(const uint32_t*)&sm[OFF_QL + ab];
            aql[1] = *(const uint32_t*)&sm[OFF_QL + ab + 8 * PADW];
            aql[2] = *(const uint32_t*)&sm[OFF_QL + ab + 8];
            aql[3] = *(const uint32_t*)&sm[OFF_QL + ab + 8 * PADW + 8];
            #pragma unroll
            for (int j = 0; j < 8; j++) {
                const int bb = (j * 8 + g) * PADW + kc * 16 + 2 * tig;
                uint32_t bkh[2], bkl[2];
                bkh[0] = *(const uint32_t*)&sm[OFF_KH + bb];
                bkh[1] = *(const uint32_t*)&sm[OFF_KH + bb + 8];
                bkl[0] = *(const uint32_t*)&sm[OFF_KL + bb];
                bkl[1] = *(const uint32_t*)&sm[OFF_KL + bb + 8];
                mma16816(sacc[j], aqh, bkh);
                mma16816(sacc[j], aql, bkh);
                mma16816(sacc[j], aqh, bkl);
            }
        }

        #pragma unroll
        for (int j = 0; j < 8; j++) {
            const int c0 = k0 + j * 8 + 2 * tig;
            if (c0 == r0)     sacc[j][0] = -1.0e9f;
            if (c0 + 1 == r0) sacc[j][1] = -1.0e9f;
            if (c0 == r1)     sacc[j][2] = -1.0e9f;
            if (c0 + 1 == r1) sacc[j][3] = -1.0e9f;
        }

        float mt0 = sacc[0][0], mt1 = sacc[0][2];
        #pragma unroll
        for (int j = 0; j < 8; j++) {
            mt0 = fmaxf(mt0, fmaxf(sacc[j][0], sacc[j][1]));
            mt1 = fmaxf(mt1, fmaxf(sacc[j][2], sacc[j][3]));
        }
        mt0 = fmaxf(mt0, __shfl_xor_sync(0xffffffffu, mt0, 1));
        mt0 = fmaxf(mt0, __shfl_xor_sync(0xffffffffu, mt0, 2));
        mt1 = fmaxf(mt1, __shfl_xor_sync(0xffffffffu, mt1, 1));
        mt1 = fmaxf(mt1, __shfl_xor_sync(0xffffffffu, mt1, 2));
        const float mn0 = fmaxf(m0r, mt0);
        const float mn1 = fmaxf(m1r, mt1);
        const float corr0 = __expf(m0r - mn0);
        const float corr1 = __expf(m1r - mn1);
        m0r = mn0; m1r = mn1;

        float rs0 = 0.0f, rs1 = 0.0f;
        #pragma unroll
        for (int j = 0; j < 8; j++) {
            sacc[j][0] = __expf(sacc[j][0] - mn0);
            sacc[j][1] = __expf(sacc[j][1] - mn0);
            sacc[j][2] = __expf(sacc[j][2] - mn1);
            sacc[j][3] = __expf(sacc[j][3] - mn1);
            rs0 += sacc[j][0] + sacc[j][1];
            rs1 += sacc[j][2] + sacc[j][3];
        }
        rs0 += __shfl_xor_sync(0xffffffffu, rs0, 1);
        rs0 += __shfl_xor_sync(0xffffffffu, rs0, 2);
        rs1 += __shfl_xor_sync(0xffffffffu, rs1, 1);
        rs1 += __shfl_xor_sync(0xffffffffu, rs1, 2);
        l0 = l0 * corr0 + rs0;
        l1 = l1 * corr1 + rs1;

        #pragma unroll
        for (int j = 0; j < 8; j++) {
            oacc[j][0] *= corr0; oacc[j][1] *= corr0;
            oacc[j][2] *= corr1; oacc[j][3] *= corr1;
        }

        #pragma unroll
        for (int kc = 0; kc < 4; kc++) {
            const int j0 = 2 * kc, j1 = 2 * kc + 1;
            uint32_t aph[4], apl[4];
            split2(sacc[j0][0], sacc[j0][1], aph[0], apl[0]);
            split2(sacc[j0][2], sacc[j0][3], aph[1], apl[1]);
            split2(sacc[j1][0], sacc[j1][1], aph[2], apl[2]);
            split2(sacc[j1][2], sacc[j1][3], aph[3], apl[3]);
            #pragma unroll
            for (int j = 0; j < 8; j++) {
                const int bb = (j * 8 + g) * PADW + kc * 16 + 2 * tig;
                uint32_t bvh[2], bvl[2];
                bvh[0] = *(const uint32_t*)&sm[OFF_VH + bb];
                bvh[1] = *(const uint32_t*)&sm[OFF_VH + bb + 8];
                bvl[0] = *(const uint32_t*)&sm[OFF_VL + bb];
                bvl[1] = *(const uint32_t*)&sm[OFF_VL + bb + 8];
                mma16816(oacc[j], aph, bvh);
                mma16816(oacc[j], apl, bvh);
                mma16816(oacc[j], aph, bvl);
            }
        }
    }

    // ---- epilogue: ctx split-bf16 [b][n][h*64+d] ----
    const int bb = bh >> 3, h = bh & 7;
    const float inv0 = 1.0f / l0;
    const float inv1 = 1.0f / l1;
    size_t base0 = ((size_t)bb * NSEQ + r0) * HD + h * DDIM;
    size_t base1 = ((size_t)bb * NSEQ + r1) * HD + h * DDIM;
    #pragma unroll
    for (int j = 0; j < 8; j++) {
        const int c = j * 8 + 2 * tig;
        uint32_t hi, lo;
        split2(oacc[j][0] * inv0, oacc[j][1] * inv0, hi, lo);
        *(uint32_t*)&g_Ch[base0 + c] = hi;
        *(uint32_t*)&g_Cl[base0 + c] = lo;
        split2(oacc[j][2] * inv1, oacc[j][3] * inv1, hi, lo);
        *(uint32_t*)&g_Ch[base1 + c] = hi;
        *(uint32_t*)&g_Cl[base1 + c] = lo;
    }
}

// ---------------------------------------------------------------------------
// Kernel 3: out = ctx @ Wo via mma.sync. CTA 128x64, K=512 in 8 chunks.
// grid (128), block 256.
// ---------------------------------------------------------------------------
#define PJ_AH 0
#define PJ_AL 9216
#define PJ_BH 18432
#define PJ_BL 23040
#define PJ_SMEM_BYTES (27648 * 2)

__global__ void __launch_bounds__(256, 2)
proj_kernel(float* __restrict__ out)
{
    extern __shared__ __nv_bfloat16 sm[];

    const int tid  = threadIdx.x;
    const int wid  = tid >> 5;
    const int lane = tid & 31;
    const int g    = lane >> 2;
    const int tig  = lane & 3;
    const int m0   = blockIdx.x * 128;

    float sacc[8][4];
    #pragma unroll
    for (int j = 0; j < 8; j++)
        #pragma unroll
        for (int t = 0; t < 4; t++) sacc[j][t] = 0.0f;

    const int aoff = (wid * 16 + g) * PADW + 2 * tig;

    for (int c0 = 0; c0 < 8; c0++) {
        const int k0 = c0 * 64;
        __syncthreads();
        for (int f = tid; f < 1024; f += 256) {
            int r = f >> 3, c = (f & 7) << 3;
            *(uint4*)&sm[PJ_AH + r * PADW + c] = *(const uint4*)(g_Ch + (size_t)(m0 + r) * HD + k0 + c);
            *(uint4*)&sm[PJ_AL + r * PADW + c] = *(const uint4*)(g_Cl + (size_t)(m0 + r) * HD + k0 + c);
        }
        for (int f = tid; f < 512; f += 256) {
            int r = f >> 3, c = (f & 7) << 3;
            *(uint4*)&sm[PJ_BH + r * PADW + c] = *(const uint4*)(g_Woth + (size_t)r * HD + k0 + c);
            *(uint4*)&sm[PJ_BL + r * PADW + c] = *(const uint4*)(g_Wotl + (size_t)r * HD + k0 + c);
        }
        __syncthreads();

        #pragma unroll
        for (int kc = 0; kc < 4; kc++) {
            uint32_t ah[4], al[4];
            const int ab = aoff + kc * 16;
            ah[0] = *(const uint32_t*)&sm[PJ_AH + ab];
            ah[1] = *(const uint32_t*)&sm[PJ_AH + ab + 8 * PADW];
            ah[2] = *(const uint32_t*)&sm[PJ_AH + ab + 8];
            ah[3] = *(const uint32_t*)&sm[PJ_AH + ab + 8 * PADW + 8];
            al[0] = *(const uint32_t*)&sm[PJ_AL + ab];
            al[1] = *(const uint32_t*)&sm[PJ_AL + ab + 8 * PADW];
            al[2] = *(const uint32_t*)&sm[PJ_AL + ab + 8];
            al[3] = *(const uint32_t*)&sm[PJ_AL + ab + 8 * PADW + 8];
            #pragma unroll
            for (int j = 0; j < 8; j++) {
                const int bb = (j * 8 + g) * PADW + kc * 16 + 2 * tig;
                uint32_t bh[2], bl[2];
                bh[0] = *(const uint32_t*)&sm[PJ_BH + bb];
                bh[1] = *(const uint32_t*)&sm[PJ_BH + bb + 8];
                bl[0] = *(const uint32_t*)&sm[PJ_BL + bb];
                bl[1] = *(const uint32_t*)&sm[PJ_BL + bb + 8];
                mma16816(sacc[j], ah, bh);
                mma16816(sacc[j], al, bh);
                mma16816(sacc[j], ah, bl);
            }
        }
    }

    const int r0 = m0 + wid * 16 + g;
    const int r1 = r0 + 8;
    #pragma unroll
    for (int j = 0; j < 8; j++) {
        const int c = j * 8 + 2 * tig;
        *(float2*)(out + (size_t)r0 * DDIM + c) = make_float2(sacc[j][0], sacc[j][1]);
        *(float2*)(out + (size_t)r1 * DDIM + c) = make_float2(sacc[j][2], sacc[j][3]);
    }
}

// ---------------------------------------------------------------------------
extern "C" void kernel_launch(void* const* d_in, const int* in_sizes, int n_in,
                              void* d_out, int out_size)
{
    const float* msg = (const float*)d_in[0];
    const float* Wq  = (const float*)d_in[1];
    const float* bq  = (const float*)d_in[2];
    const float* Wk  = (const float*)d_in[3];
    const float* bk  = (const float*)d_in[4];
    const float* Wv  = (const float*)d_in[5];
    const float* bv  = (const float*)d_in[6];
    const float* Wo  = (const float*)d_in[7];
    float* out = (float*)d_out;

    cudaFuncSetAttribute(qkv_kernel,  cudaFuncAttributeMaxDynamicSharedMemorySize, QK_SMEM_BYTES);
    cudaFuncSetAttribute(attn_kernel, cudaFuncAttributeMaxDynamicSharedMemorySize, ATTN_SMEM_BYTES);
    cudaFuncSetAttribute(proj_kernel, cudaFuncAttributeMaxDynamicSharedMemorySize, PJ_SMEM_BYTES);

    conv_kernel<<<2048, 256>>>(msg, Wq, Wk, Wv, Wo);
    qkv_kernel<<<dim3(128, 4, 3), 256, QK_SMEM_BYTES>>>(bq, bk, bv);
    attn_kernel<<<dim3(NB * NH, NSEQ / BM), 256, ATTN_SMEM_BYTES>>>();
    proj_kernel<<<dim3(128, 1, 1), 256, PJ_SMEM_BYTES>>>(out);
}

// round 5
// speedup vs baseline: 3.6123x; 1.1298x over previous
#include <cuda_runtime.h>
#include <cuda_bf16.h>
#include <cstdint>

#define NSEQ 2048
#define DDIM 64
#define NH 8
#define NB 8
#define HD 512      // NH * DDIM
#define INDIM 256
#define BM 128      // queries per CTA (8 warps x 16 rows)
#define BN 64       // keys per tile
#define PADW 72     // padded bf16 row width (conflict-free)

// ---------------- scratch (allocation-free __device__ globals) ----------------
__device__ __nv_bfloat16 g_Mh[NB * NSEQ * INDIM];      // msg split
__device__ __nv_bfloat16 g_Ml[NB * NSEQ * INDIM];
__device__ __nv_bfloat16 g_Wth[3 * HD * INDIM];        // W^T per z: [z][n=512][k=256]
__device__ __nv_bfloat16 g_Wtl[3 * HD * INDIM];
__device__ __nv_bfloat16 g_Woth[DDIM * HD];            // Wo^T: [n=64][k=512]
__device__ __nv_bfloat16 g_Wotl[DDIM * HD];

__device__ __nv_bfloat16 g_Qh[NB * NH * NSEQ * DDIM];  // [b][h][n][d], pre-scaled 0.125*log2e
__device__ __nv_bfloat16 g_Ql[NB * NH * NSEQ * DDIM];
__device__ __nv_bfloat16 g_Kh[NB * NH * NSEQ * DDIM];
__device__ __nv_bfloat16 g_Kl[NB * NH * NSEQ * DDIM];
__device__ __nv_bfloat16 g_Vth[NB * NH * DDIM * NSEQ]; // transposed: [b][h][d][n]
__device__ __nv_bfloat16 g_Vtl[NB * NH * DDIM * NSEQ];
__device__ __nv_bfloat16 g_Ch[NB * NSEQ * HD];         // ctx split: [b][n][h*64+d]
__device__ __nv_bfloat16 g_Cl[NB * NSEQ * HD];

// ---------------- mma.sync / PTX helpers (baseline PTX, sm_103-safe) ----------
__device__ __forceinline__ void mma16816(float* d, const uint32_t* a, const uint32_t* b) {
    asm volatile(
        "mma.sync.aligned.m16n8k16.row.col.f32.bf16.bf16.f32 "
        "{%0,%1,%2,%3}, {%4,%5,%6,%7}, {%8,%9}, {%0,%1,%2,%3};"
        : "+f"(d[0]), "+f"(d[1]), "+f"(d[2]), "+f"(d[3])
        : "r"(a[0]), "r"(a[1]), "r"(a[2]), "r"(a[3]), "r"(b[0]), "r"(b[1]));
}
__device__ __forceinline__ uint32_t pack_bf16(float e0, float e1) {
    uint32_t r;
    asm("cvt.rn.bf16x2.f32 %0, %1, %2;" : "=r"(r) : "f"(e1), "f"(e0));
    return r;
}
__device__ __forceinline__ void split2(float v0, float v1, uint32_t& hi, uint32_t& lo) {
    hi = pack_bf16(v0, v1);
    float r0 = v0 - __uint_as_float(hi << 16);
    float r1 = v1 - __uint_as_float(hi & 0xffff0000u);
    lo = pack_bf16(r0, r1);
}
__device__ __forceinline__ float ex2(float x) {
    float r;
    asm("ex2.approx.ftz.f32 %0, %1;" : "=f"(r) : "f"(x));
    return r;
}
__device__ __forceinline__ uint32_t smem_u32(const void* p) {
    uint32_t a;
    asm("{ .reg .u64 t; cvta.to.shared.u64 t, %1; cvt.u32.u64 %0, t; }" : "=r"(a) : "l"(p));
    return a;
}
__device__ __forceinline__ void cp16(uint32_t s, const void* g) {
    asm volatile("cp.async.cg.shared.global [%0], [%1], 16;" :: "r"(s), "l"(g));
}
#define CP_COMMIT() asm volatile("cp.async.commit_group;" ::: "memory")
#define CP_WAIT0()  asm volatile("cp.async.wait_group 0;" ::: "memory")

// ---------------------------------------------------------------------------
// Kernel 0: fp32 -> split-bf16 conversions (msg, W^T x3, Wo^T)
// ---------------------------------------------------------------------------
__global__ void __launch_bounds__(256)
conv_kernel(const float* __restrict__ msg,
            const float* __restrict__ Wq, const float* __restrict__ Wk,
            const float* __restrict__ Wv, const float* __restrict__ Wo)
{
    const int stride = gridDim.x * blockDim.x;
    const int gid = blockIdx.x * blockDim.x + threadIdx.x;

    for (int i = gid; i < NB * NSEQ * INDIM; i += stride) {
        float v = msg[i];
        __nv_bfloat16 hi = __float2bfloat16_rn(v);
        g_Mh[i] = hi;
        g_Ml[i] = __float2bfloat16_rn(v - __bfloat162float(hi));
    }
    for (int i = gid; i < HD * INDIM; i += stride) {
        int n = i / INDIM, k = i % INDIM;
        #pragma unroll
        for (int z = 0; z < 3; z++) {
            const float* W = (z == 0) ? Wq : (z == 1) ? Wk : Wv;
            float v = W[(size_t)k * HD + n];
            __nv_bfloat16 hi = __float2bfloat16_rn(v);
            g_Wth[z * HD * INDIM + i] = hi;
            g_Wtl[z * HD * INDIM + i] = __float2bfloat16_rn(v - __bfloat162float(hi));
        }
    }
    for (int i = gid; i < DDIM * HD; i += stride) {
        int n = i / HD, k = i % HD;
        float v = Wo[(size_t)k * DDIM + n];
        __nv_bfloat16 hi = __float2bfloat16_rn(v);
        g_Woth[i] = hi;
        g_Wotl[i] = __float2bfloat16_rn(v - __bfloat162float(hi));
    }
}

// ---------------------------------------------------------------------------
// Kernel 1: QKV projection via mma.sync. CTA 128x128, warp 16x128, K=256.
// ---------------------------------------------------------------------------
#define QK_AH 0
#define QK_AL 9216
#define QK_BH 18432
#define QK_BL 27648
#define QK_SMEM_BYTES (36864 * 2)

__global__ void __launch_bounds__(256, 2)
qkv_kernel(const float* __restrict__ bq, const float* __restrict__ bk,
           const float* __restrict__ bv)
{
    extern __shared__ __nv_bfloat16 sm[];

    const int tid  = threadIdx.x;
    const int wid  = tid >> 5;
    const int lane = tid & 31;
    const int g    = lane >> 2;
    const int tig  = lane & 3;
    const int z    = blockIdx.z;
    const int m0   = blockIdx.x * 128;
    const int n0   = blockIdx.y * 128;

    const float* __restrict__ bias = (z == 0) ? bq : (z == 1) ? bk : bv;
    const __nv_bfloat16* __restrict__ gBh = g_Wth + (size_t)z * HD * INDIM;
    const __nv_bfloat16* __restrict__ gBl = g_Wtl + (size_t)z * HD * INDIM;

    float sacc[16][4];
    #pragma unroll
    for (int j = 0; j < 16; j++)
        #pragma unroll
        for (int t = 0; t < 4; t++) sacc[j][t] = 0.0f;

    const int aoff = (wid * 16 + g) * PADW + 2 * tig;

    for (int c0 = 0; c0 < 4; c0++) {
        const int k0 = c0 * 64;
        __syncthreads();
        for (int f = tid; f < 1024; f += 256) {
            int r = f >> 3, c = (f & 7) << 3;
            *(uint4*)&sm[QK_AH + r * PADW + c] = *(const uint4*)(g_Mh + (size_t)(m0 + r) * INDIM + k0 + c);
            *(uint4*)&sm[QK_AL + r * PADW + c] = *(const uint4*)(g_Ml + (size_t)(m0 + r) * INDIM + k0 + c);
            *(uint4*)&sm[QK_BH + r * PADW + c] = *(const uint4*)(gBh + (size_t)(n0 + r) * INDIM + k0 + c);
            *(uint4*)&sm[QK_BL + r * PADW + c] = *(const uint4*)(gBl + (size_t)(n0 + r) * INDIM + k0 + c);
        }
        __syncthreads();

        #pragma unroll
        for (int kc = 0; kc < 4; kc++) {
            uint32_t ah[4], al[4];
            const int ab = aoff + kc * 16;
            ah[0] = *(const uint32_t*)&sm[QK_AH + ab];
            ah[1] = *(const uint32_t*)&sm[QK_AH + ab + 8 * PADW];
            ah[2] = *(const uint32_t*)&sm[QK_AH + ab + 8];
            ah[3] = *(const uint32_t*)&sm[QK_AH + ab + 8 * PADW + 8];
            al[0] = *(const uint32_t*)&sm[QK_AL + ab];
            al[1] = *(const uint32_t*)&sm[QK_AL + ab + 8 * PADW];
            al[2] = *(const uint32_t*)&sm[QK_AL + ab + 8];
            al[3] = *(const uint32_t*)&sm[QK_AL + ab + 8 * PADW + 8];
            #pragma unroll
            for (int j = 0; j < 16; j++) {
                const int bb = (j * 8 + g) * PADW + kc * 16 + 2 * tig;
                uint32_t bh[2], bl[2];
                bh[0] = *(const uint32_t*)&sm[QK_BH + bb];
                bh[1] = *(const uint32_t*)&sm[QK_BH + bb + 8];
                bl[0] = *(const uint32_t*)&sm[QK_BL + bb];
                bl[1] = *(const uint32_t*)&sm[QK_BL + bb + 8];
                mma16816(sacc[j], ah, bh);
                mma16816(sacc[j], al, bh);
                mma16816(sacc[j], ah, bl);
            }
        }
    }

    // ---- epilogue: bias + qscale (Q folded with log2e), split, scatter ----
    const float qscale = (z == 0) ? 0.18033688011112042f : 1.0f;  // 0.125*log2(e)
    const int r0 = m0 + wid * 16 + g;
    const int r1 = r0 + 8;
    const int bb0 = r0 >> 11, nn0 = r0 & (NSEQ - 1);
    const int bb1 = r1 >> 11, nn1 = r1 & (NSEQ - 1);

    #pragma unroll
    for (int j = 0; j < 16; j++) {
        const int cg = n0 + j * 8 + 2 * tig;
        const int h = cg >> 6, d = cg & 63;
        const float b0 = bias[cg], b1 = bias[cg + 1];
        float v00 = (sacc[j][0] + b0) * qscale, v01 = (sacc[j][1] + b1) * qscale;
        float v10 = (sacc[j][2] + b0) * qscale, v11 = (sacc[j][3] + b1) * qscale;
        uint32_t hi0, lo0, hi1, lo1;
        split2(v00, v01, hi0, lo0);
        split2(v10, v11, hi1, lo1);

        if (z == 2) {
            size_t base0 = ((size_t)(bb0 * NH + h) * DDIM + d) * NSEQ + nn0;
            size_t base1 = ((size_t)(bb1 * NH + h) * DDIM + d) * NSEQ + nn1;
            g_Vth[base0]        = __ushort_as_bfloat16((unsigned short)(hi0 & 0xffff));
            g_Vth[base0 + NSEQ] = __ushort_as_bfloat16((unsigned short)(hi0 >> 16));
            g_Vtl[base0]        = __ushort_as_bfloat16((unsigned short)(lo0 & 0xffff));
            g_Vtl[base0 + NSEQ] = __ushort_as_bfloat16((unsigned short)(lo0 >> 16));
            g_Vth[base1]        = __ushort_as_bfloat16((unsigned short)(hi1 & 0xffff));
            g_Vth[base1 + NSEQ] = __ushort_as_bfloat16((unsigned short)(hi1 >> 16));
            g_Vtl[base1]        = __ushort_as_bfloat16((unsigned short)(lo1 & 0xffff));
            g_Vtl[base1 + NSEQ] = __ushort_as_bfloat16((unsigned short)(lo1 >> 16));
        } else {
            __nv_bfloat16* dh = (z == 0) ? g_Qh : g_Kh;
            __nv_bfloat16* dl = (z == 0) ? g_Ql : g_Kl;
            size_t i0 = ((size_t)(bb0 * NH + h) * NSEQ + nn0) * DDIM + d;
            size_t i1 = ((size_t)(bb1 * NH + h) * NSEQ + nn1) * DDIM + d;
            *(uint32_t*)&dh[i0] = hi0; *(uint32_t*)&dl[i0] = lo0;
            *(uint32_t*)&dh[i1] = hi1; *(uint32_t*)&dl[i1] = lo1;
        }
    }
}

// ---------------------------------------------------------------------------
// Kernel 2: flash attention, cp.async double-buffered K/V, Q frags in regs.
// smem: 2 x (KH|KL|VH|VL) buffers, each array 64 x PADW bf16. 73,728 B total.
// ---------------------------------------------------------------------------
#define E_KH 0
#define E_KL 4608
#define E_VH 9216
#define E_VL 13824
#define BUF_ELEMS 18432
#define BUF_BYTES 36864
#define ATTN_SMEM_BYTES (2 * BUF_BYTES)
#define NT (NSEQ / BN)

__global__ void __launch_bounds__(256, 2)
attn_kernel()
{
    extern __shared__ __nv_bfloat16 sm[];

    const int tid  = threadIdx.x;
    const int wid  = tid >> 5;
    const int lane = tid & 31;
    const int g    = lane >> 2;
    const int tig  = lane & 3;
    const int bh   = blockIdx.x;
    const int q0   = blockIdx.y * BM;

    const size_t hb = (size_t)bh * NSEQ * DDIM;
    const __nv_bfloat16* __restrict__ gkh = g_Kh + hb;
    const __nv_bfloat16* __restrict__ gkl = g_Kl + hb;
    const __nv_bfloat16* __restrict__ gvh = g_Vth + hb;   // [d][n]
    const __nv_bfloat16* __restrict__ gvl = g_Vtl + hb;

    const uint32_t smb = smem_u32(sm);
    const int r0 = q0 + wid * 16 + g;
    const int r1 = r0 + 8;

    // ---- Q A-fragments: load once, straight from gmem ----
    uint32_t qfh[4][4], qfl[4][4];
    {
        const __nv_bfloat16* qh = g_Qh + hb;
        const __nv_bfloat16* ql = g_Ql + hb;
        #pragma unroll
        for (int kc = 0; kc < 4; kc++) {
            const int c = kc * 16 + 2 * tig;
            qfh[kc][0] = *(const uint32_t*)(qh + (size_t)r0 * DDIM + c);
            qfh[kc][1] = *(const uint32_t*)(qh + (size_t)r1 * DDIM + c);
            qfh[kc][2] = *(const uint32_t*)(qh + (size_t)r0 * DDIM + c + 8);
            qfh[kc][3] = *(const uint32_t*)(qh + (size_t)r1 * DDIM + c + 8);
            qfl[kc][0] = *(const uint32_t*)(ql + (size_t)r0 * DDIM + c);
            qfl[kc][1] = *(const uint32_t*)(ql + (size_t)r1 * DDIM + c);
            qfl[kc][2] = *(const uint32_t*)(ql + (size_t)r0 * DDIM + c + 8);
            qfl[kc][3] = *(const uint32_t*)(ql + (size_t)r1 * DDIM + c + 8);
        }
    }

    // ---- async K/V tile prefetch ----
    auto issue_kv = [&](int kt) {
        const int k0 = kt * BN;
        const uint32_t bufb = smb + (uint32_t)((kt & 1) * BUF_BYTES);
        #pragma unroll
        for (int f = tid; f < 512; f += 256) {
            const int r = f >> 3, c = (f & 7) << 3;
            const uint32_t ro = (uint32_t)(r * PADW + c) * 2;
            cp16(bufb + 2 * E_KH + ro, gkh + (size_t)(k0 + r) * DDIM + c);
            cp16(bufb + 2 * E_KL + ro, gkl + (size_t)(k0 + r) * DDIM + c);
            cp16(bufb + 2 * E_VH + ro, gvh + (size_t)r * NSEQ + k0 + c);
            cp16(bufb + 2 * E_VL + ro, gvl + (size_t)r * NSEQ + k0 + c);
        }
        CP_COMMIT();
    };

    issue_kv(0);

    float oacc[8][4];
    #pragma unroll
    for (int j = 0; j < 8; j++)
        #pragma unroll
        for (int t = 0; t < 4; t++) oacc[j][t] = 0.0f;
    float m0r = -3.0e38f, m1r = -3.0e38f, l0 = 0.0f, l1 = 0.0f;

    for (int kt = 0; kt < NT; kt++) {
        const int k0 = kt * BN;
        CP_WAIT0();
        __syncthreads();       // tile kt visible to all; all done with buf[kt&1] from kt-2
        if (kt + 1 < NT) issue_kv(kt + 1);

        const __nv_bfloat16* bufp = sm + (kt & 1) * BUF_ELEMS;

        // ---- S = Qh*Kh + Ql*Kh + Qh*Kl ----
        float sacc[8][4];
        #pragma unroll
        for (int j = 0; j < 8; j++)
            #pragma unroll
            for (int t = 0; t < 4; t++) sacc[j][t] = 0.0f;

        #pragma unroll
        for (int kc = 0; kc < 4; kc++) {
            #pragma unroll
            for (int j = 0; j < 8; j++) {
                const int bb = (j * 8 + g) * PADW + kc * 16 + 2 * tig;
                uint32_t bkh[2], bkl[2];
                bkh[0] = *(const uint32_t*)&bufp[E_KH + bb];
                bkh[1] = *(const uint32_t*)&bufp[E_KH + bb + 8];
                bkl[0] = *(const uint32_t*)&bufp[E_KL + bb];
                bkl[1] = *(const uint32_t*)&bufp[E_KL + bb + 8];
                mma16816(sacc[j], qfh[kc], bkh);
                mma16816(sacc[j], qfl[kc], bkh);
                mma16816(sacc[j], qfh[kc], bkl);
            }
        }

        // ---- exclude-self mask ----
        #pragma unroll
        for (int j = 0; j < 8; j++) {
            const int cc = k0 + j * 8 + 2 * tig;
            if (cc == r0)     sacc[j][0] = -1.0e9f;
            if (cc + 1 == r0) sacc[j][1] = -1.0e9f;
            if (cc == r1)     sacc[j][2] = -1.0e9f;
            if (cc + 1 == r1) sacc[j][3] = -1.0e9f;
        }

        // ---- online softmax in base-2 domain (scores pre-scaled by log2e) ----
        float mt0 = sacc[0][0], mt1 = sacc[0][2];
        #pragma unroll
        for (int j = 0; j < 8; j++) {
            mt0 = fmaxf(mt0, fmaxf(sacc[j][0], sacc[j][1]));
            mt1 = fmaxf(mt1, fmaxf(sacc[j][2], sacc[j][3]));
        }
        mt0 = fmaxf(mt0, __shfl_xor_sync(0xffffffffu, mt0, 1));
        mt0 = fmaxf(mt0, __shfl_xor_sync(0xffffffffu, mt0, 2));
        mt1 = fmaxf(mt1, __shfl_xor_sync(0xffffffffu, mt1, 1));
        mt1 = fmaxf(mt1, __shfl_xor_sync(0xffffffffu, mt1, 2));
        const float mn0 = fmaxf(m0r, mt0);
        const float mn1 = fmaxf(m1r, mt1);
        const float corr0 = ex2(m0r - mn0);
        const float corr1 = ex2(m1r - mn1);
        m0r = mn0; m1r = mn1;

        float rs0 = 0.0f, rs1 = 0.0f;
        #pragma unroll
        for (int j = 0; j < 8; j++) {
            sacc[j][0] = ex2(sacc[j][0] - mn0);
            sacc[j][1] = ex2(sacc[j][1] - mn0);
            sacc[j][2] = ex2(sacc[j][2] - mn1);
            sacc[j][3] = ex2(sacc[j][3] - mn1);
            rs0 += sacc[j][0] + sacc[j][1];
            rs1 += sacc[j][2] + sacc[j][3];
        }
        rs0 += __shfl_xor_sync(0xffffffffu, rs0, 1);
        rs0 += __shfl_xor_sync(0xffffffffu, rs0, 2);
        rs1 += __shfl_xor_sync(0xffffffffu, rs1, 1);
        rs1 += __shfl_xor_sync(0xffffffffu, rs1, 2);
        l0 = l0 * corr0 + rs0;
        l1 = l1 * corr1 + rs1;

        #pragma unroll
        for (int j = 0; j < 8; j++) {
            oacc[j][0] *= corr0; oacc[j][1] *= corr0;
            oacc[j][2] *= corr1; oacc[j][3] *= corr1;
        }

        // ---- O += P @ V (P split to bf16 hi/lo in registers) ----
        #pragma unroll
        for (int kc = 0; kc < 4; kc++) {
            const int j0 = 2 * kc, j1 = 2 * kc + 1;
            uint32_t aph[4], apl[4];
            split2(sacc[j0][0], sacc[j0][1], aph[0], apl[0]);
            split2(sacc[j0][2], sacc[j0][3], aph[1], apl[1]);
            split2(sacc[j1][0], sacc[j1][1], aph[2], apl[2]);
            split2(sacc[j1][2], sacc[j1][3], aph[3], apl[3]);
            #pragma unroll
            for (int j = 0; j < 8; j++) {
                const int bb = (j * 8 + g) * PADW + kc * 16 + 2 * tig;
                uint32_t bvh[2], bvl[2];
                bvh[0] = *(const uint32_t*)&bufp[E_VH + bb];
                bvh[1] = *(const uint32_t*)&bufp[E_VH + bb + 8];
                bvl[0] = *(const uint32_t*)&bufp[E_VL + bb];
                bvl[1] = *(const uint32_t*)&bufp[E_VL + bb + 8];
                mma16816(oacc[j], aph, bvh);
                mma16816(oacc[j], apl, bvh);
                mma16816(oacc[j], aph, bvl);
            }
        }
    }

    // ---- epilogue: ctx split-bf16 [b][n][h*64+d] ----
    const int bb = bh >> 3, h = bh & 7;
    const float inv0 = 1.0f / l0;
    const float inv1 = 1.0f / l1;
    size_t base0 = ((size_t)bb * NSEQ + r0) * HD + h * DDIM;
    size_t base1 = ((size_t)bb * NSEQ + r1) * HD + h * DDIM;
    #pragma unroll
    for (int j = 0; j < 8; j++) {
        const int c = j * 8 + 2 * tig;
        uint32_t hi, lo;
        split2(oacc[j][0] * inv0, oacc[j][1] * inv0, hi, lo);
        *(uint32_t*)&g_Ch[base0 + c] = hi;
        *(uint32_t*)&g_Cl[base0 + c] = lo;
        split2(oacc[j][2] * inv1, oacc[j][3] * inv1, hi, lo);
        *(uint32_t*)&g_Ch[base1 + c] = hi;
        *(uint32_t*)&g_Cl[base1 + c] = lo;
    }
}

// ---------------------------------------------------------------------------
// Kernel 3: out = ctx @ Wo. CTA 64x64 (4 warps), grid 256 for occupancy.
// ---------------------------------------------------------------------------
#define PJ_AH 0
#define PJ_AL 4608
#define PJ_BH 9216
#define PJ_BL 13824
#define PJ_SMEM_BYTES (18432 * 2)

__global__ void __launch_bounds__(128)
proj_kernel(float* __restrict__ out)
{
    extern __shared__ __nv_bfloat16 sm[];

    const int tid  = threadIdx.x;
    const int wid  = tid >> 5;
    const int lane = tid & 31;
    const int g    = lane >> 2;
    const int tig  = lane & 3;
    const int m0   = blockIdx.x * 64;

    float sacc[8][4];
    #pragma unroll
    for (int j = 0; j < 8; j++)
        #pragma unroll
        for (int t = 0; t < 4; t++) sacc[j][t] = 0.0f;

    const int aoff = (wid * 16 + g) * PADW + 2 * tig;

    for (int c0 = 0; c0 < 8; c0++) {
        const int k0 = c0 * 64;
        __syncthreads();
        for (int f = tid; f < 512; f += 128) {
            int r = f >> 3, c = (f & 7) << 3;
            *(uint4*)&sm[PJ_AH + r * PADW + c] = *(const uint4*)(g_Ch + (size_t)(m0 + r) * HD + k0 + c);
            *(uint4*)&sm[PJ_AL + r * PADW + c] = *(const uint4*)(g_Cl + (size_t)(m0 + r) * HD + k0 + c);
            *(uint4*)&sm[PJ_BH + r * PADW + c] = *(const uint4*)(g_Woth + (size_t)r * HD + k0 + c);
            *(uint4*)&sm[PJ_BL + r * PADW + c] = *(const uint4*)(g_Wotl + (size_t)r * HD + k0 + c);
        }
        __syncthreads();

        #pragma unroll
        for (int kc = 0; kc < 4; kc++) {
            uint32_t ah[4], al[4];
            const int ab = aoff + kc * 16;
            ah[0] = *(const uint32_t*)&sm[PJ_AH + ab];
            ah[1] = *(const uint32_t*)&sm[PJ_AH + ab + 8 * PADW];
            ah[2] = *(const uint32_t*)&sm[PJ_AH + ab + 8];
            ah[3] = *(const uint32_t*)&sm[PJ_AH + ab + 8 * PADW + 8];
            al[0] = *(const uint32_t*)&sm[PJ_AL + ab];
            al[1] = *(const uint32_t*)&sm[PJ_AL + ab + 8 * PADW];
            al[2] = *(const uint32_t*)&sm[PJ_AL + ab + 8];
            al[3] = *(const uint32_t*)&sm[PJ_AL + ab + 8 * PADW + 8];
            #pragma unroll
            for (int j = 0; j < 8; j++) {
                const int bb = (j * 8 + g) * PADW + kc * 16 + 2 * tig;
                uint32_t bh[2], bl[2];
                bh[0] = *(const uint32_t*)&sm[PJ_BH + bb];
                bh[1] = *(const uint32_t*)&sm[PJ_BH + bb + 8];
                bl[0] = *(const uint32_t*)&sm[PJ_BL + bb];
                bl[1] = *(const uint32_t*)&sm[PJ_BL + bb + 8];
                mma16816(sacc[j], ah, bh);
                mma16816(sacc[j], al, bh);
                mma16816(sacc[j], ah, bl);
            }
        }
    }

    const int r0 = m0 + wid * 16 + g;
    const int r1 = r0 + 8;
    #pragma unroll
    for (int j = 0; j < 8; j++) {
        const int c = j * 8 + 2 * tig;
        *(float2*)(out + (size_t)r0 * DDIM + c) = make_float2(sacc[j][0], sacc[j][1]);
        *(float2*)(out + (size_t)r1 * DDIM + c) = make_float2(sacc[j][2], sacc[j][3]);
    }
}

// ---------------------------------------------------------------------------
extern "C" void kernel_launch(void* const* d_in, const int* in_sizes, int n_in,
                              void* d_out, int out_size)
{
    const float* msg = (const float*)d_in[0];
    const float* Wq  = (const float*)d_in[1];
    const float* bq  = (const float*)d_in[2];
    const float* Wk  = (const float*)d_in[3];
    const float* bk  = (const float*)d_in[4];
    const float* Wv  = (const float*)d_in[5];
    const float* bv  = (const float*)d_in[6];
    const float* Wo  = (const float*)d_in[7];
    float* out = (float*)d_out;

    cudaFuncSetAttribute(qkv_kernel,  cudaFuncAttributeMaxDynamicSharedMemorySize, QK_SMEM_BYTES);
    cudaFuncSetAttribute(attn_kernel, cudaFuncAttributeMaxDynamicSharedMemorySize, ATTN_SMEM_BYTES);
    cudaFuncSetAttribute(proj_kernel, cudaFuncAttributeMaxDynamicSharedMemorySize, PJ_SMEM_BYTES);

    conv_kernel<<<2048, 256>>>(msg, Wq, Wk, Wv, Wo);
    qkv_kernel<<<dim3(128, 4, 3), 256, QK_SMEM_BYTES>>>(bq, bk, bv);
    attn_kernel<<<dim3(NB * NH, NSEQ / BM), 256, ATTN_SMEM_BYTES>>>();
    proj_kernel<<<dim3(256, 1, 1), 128, PJ_SMEM_BYTES>>>(out);
}

// round 6
// speedup vs baseline: 3.7061x; 1.0260x over previous
#include <cuda_runtime.h>
#include <cuda_bf16.h>
#include <cstdint>

#define NSEQ 2048
#define DDIM 64
#define NH 8
#define NB 8
#define HD 512      // NH * DDIM
#define INDIM 256
#define BM 128      // queries per CTA (8 warps x 16 rows)
#define BN 64       // keys per tile
#define PADW 72     // padded bf16 row width (conflict-free)
#define NT (NSEQ / BN)

// ---------------- scratch (allocation-free __device__ globals) ----------------
__device__ __nv_bfloat16 g_Mh[NB * NSEQ * INDIM];      // msg split
__device__ __nv_bfloat16 g_Ml[NB * NSEQ * INDIM];
__device__ __nv_bfloat16 g_Wth[3 * HD * INDIM];        // W^T per z: [z][n=512][k=256]
__device__ __nv_bfloat16 g_Wtl[3 * HD * INDIM];
__device__ __nv_bfloat16 g_Woth[DDIM * HD];            // Wo^T: [n=64][k=512]
__device__ __nv_bfloat16 g_Wotl[DDIM * HD];

__device__ __nv_bfloat16 g_Qh[NB * NH * NSEQ * DDIM];  // [b][h][n][d], pre-scaled 0.125*log2e
__device__ __nv_bfloat16 g_Ql[NB * NH * NSEQ * DDIM];
__device__ __nv_bfloat16 g_Kh[NB * NH * NSEQ * DDIM];
__device__ __nv_bfloat16 g_Kl[NB * NH * NSEQ * DDIM];
__device__ __nv_bfloat16 g_Vth[NB * NH * DDIM * NSEQ]; // transposed: [b][h][d][n]
__device__ __nv_bfloat16 g_Vtl[NB * NH * DDIM * NSEQ];
__device__ __nv_bfloat16 g_Ch[NB * NSEQ * HD];         // ctx split: [b][n][h*64+d]
__device__ __nv_bfloat16 g_Cl[NB * NSEQ * HD];

// ---------------- mma.sync / PTX helpers (baseline PTX, sm_103-safe) ----------
__device__ __forceinline__ void mma16816(float* d, const uint32_t* a, const uint32_t* b) {
    asm volatile(
        "mma.sync.aligned.m16n8k16.row.col.f32.bf16.bf16.f32 "
        "{%0,%1,%2,%3}, {%4,%5,%6,%7}, {%8,%9}, {%0,%1,%2,%3};"
        : "+f"(d[0]), "+f"(d[1]), "+f"(d[2]), "+f"(d[3])
        : "r"(a[0]), "r"(a[1]), "r"(a[2]), "r"(a[3]), "r"(b[0]), "r"(b[1]));
}
__device__ __forceinline__ uint32_t pack_bf16(float e0, float e1) {
    uint32_t r;
    asm("cvt.rn.bf16x2.f32 %0, %1, %2;" : "=r"(r) : "f"(e1), "f"(e0));
    return r;
}
__device__ __forceinline__ void split2(float v0, float v1, uint32_t& hi, uint32_t& lo) {
    hi = pack_bf16(v0, v1);
    float r0 = v0 - __uint_as_float(hi << 16);
    float r1 = v1 - __uint_as_float(hi & 0xffff0000u);
    lo = pack_bf16(r0, r1);
}
__device__ __forceinline__ float ex2(float x) {
    float r;
    asm("ex2.approx.ftz.f32 %0, %1;" : "=f"(r) : "f"(x));
    return r;
}
__device__ __forceinline__ uint32_t smem_u32(const void* p) {
    uint32_t a;
    asm("{ .reg .u64 t; cvta.to.shared.u64 t, %1; cvt.u32.u64 %0, t; }" : "=r"(a) : "l"(p));
    return a;
}
__device__ __forceinline__ void cp16(uint32_t s, const void* g) {
    asm volatile("cp.async.cg.shared.global [%0], [%1], 16;" :: "r"(s), "l"(g));
}
#define CP_COMMIT() asm volatile("cp.async.commit_group;" ::: "memory")
#define CP_WAIT0()  asm volatile("cp.async.wait_group 0;" ::: "memory")
#define CP_WAIT1()  asm volatile("cp.async.wait_group 1;" ::: "memory")

// ---------------------------------------------------------------------------
// Kernel 0: fp32 -> split-bf16 conversions (msg, W^T x3, Wo^T)
// ---------------------------------------------------------------------------
__global__ void __launch_bounds__(256)
conv_kernel(const float* __restrict__ msg,
            const float* __restrict__ Wq, const float* __restrict__ Wk,
            const float* __restrict__ Wv, const float* __restrict__ Wo)
{
    const int stride = gridDim.x * blockDim.x;
    const int gid = blockIdx.x * blockDim.x + threadIdx.x;

    for (int i = gid; i < NB * NSEQ * INDIM; i += stride) {
        float v = msg[i];
        __nv_bfloat16 hi = __float2bfloat16_rn(v);
        g_Mh[i] = hi;
        g_Ml[i] = __float2bfloat16_rn(v - __bfloat162float(hi));
    }
    for (int i = gid; i < HD * INDIM; i += stride) {
        int n = i / INDIM, k = i % INDIM;
        #pragma unroll
        for (int z = 0; z < 3; z++) {
            const float* W = (z == 0) ? Wq : (z == 1) ? Wk : Wv;
            float v = W[(size_t)k * HD + n];
            __nv_bfloat16 hi = __float2bfloat16_rn(v);
            g_Wth[z * HD * INDIM + i] = hi;
            g_Wtl[z * HD * INDIM + i] = __float2bfloat16_rn(v - __bfloat162float(hi));
        }
    }
    for (int i = gid; i < DDIM * HD; i += stride) {
        int n = i / HD, k = i % HD;
        float v = Wo[(size_t)k * DDIM + n];
        __nv_bfloat16 hi = __float2bfloat16_rn(v);
        g_Woth[i] = hi;
        g_Wotl[i] = __float2bfloat16_rn(v - __bfloat162float(hi));
    }
}

// ---------------------------------------------------------------------------
// Kernel 1: QKV projection via mma.sync, cp.async double-buffered.
// CTA 128x64, 8 warps (warp 16x64). grid (128, 8, 3).
// ---------------------------------------------------------------------------
#define QB_AH 0
#define QB_AL 9216
#define QB_BH 18432
#define QB_BL 23040
#define QB_ELEMS 27648
#define QB_BYTES 55296
#define QK_SMEM_BYTES (2 * QB_BYTES)

__global__ void __launch_bounds__(256, 2)
qkv_kernel(const float* __restrict__ bq, const float* __restrict__ bk,
           const float* __restrict__ bv)
{
    extern __shared__ __nv_bfloat16 sm[];

    const int tid  = threadIdx.x;
    const int wid  = tid >> 5;
    const int lane = tid & 31;
    const int g    = lane >> 2;
    const int tig  = lane & 3;
    const int z    = blockIdx.z;
    const int m0   = blockIdx.x * 128;
    const int n0   = blockIdx.y * 64;

    const float* __restrict__ bias = (z == 0) ? bq : (z == 1) ? bk : bv;
    const __nv_bfloat16* __restrict__ gBh = g_Wth + (size_t)z * HD * INDIM;
    const __nv_bfloat16* __restrict__ gBl = g_Wtl + (size_t)z * HD * INDIM;

    const uint32_t smb = smem_u32(sm);

    auto issue = [&](int c) {
        const int k0 = c * 64;
        const uint32_t bufb = smb + (uint32_t)((c & 1) * QB_BYTES);
        for (int f = tid; f < 1024; f += 256) {
            const int r = f >> 3, cc = (f & 7) << 3;
            const uint32_t ro = (uint32_t)(r * PADW + cc) * 2;
            cp16(bufb + 2 * QB_AH + ro, g_Mh + (size_t)(m0 + r) * INDIM + k0 + cc);
            cp16(bufb + 2 * QB_AL + ro, g_Ml + (size_t)(m0 + r) * INDIM + k0 + cc);
        }
        for (int f = tid; f < 512; f += 256) {
            const int r = f >> 3, cc = (f & 7) << 3;
            const uint32_t ro = (uint32_t)(r * PADW + cc) * 2;
            cp16(bufb + 2 * QB_BH + ro, gBh + (size_t)(n0 + r) * INDIM + k0 + cc);
            cp16(bufb + 2 * QB_BL + ro, gBl + (size_t)(n0 + r) * INDIM + k0 + cc);
        }
        CP_COMMIT();
    };

    issue(0);

    float sacc[8][4];
    #pragma unroll
    for (int j = 0; j < 8; j++)
        #pragma unroll
        for (int t = 0; t < 4; t++) sacc[j][t] = 0.0f;

    const int aoff = (wid * 16 + g) * PADW + 2 * tig;

    for (int c0 = 0; c0 < 4; c0++) {
        CP_WAIT0();
        __syncthreads();
        if (c0 + 1 < 4) issue(c0 + 1);

        const __nv_bfloat16* bufp = sm + (c0 & 1) * QB_ELEMS;

        #pragma unroll
        for (int kc = 0; kc < 4; kc++) {
            uint32_t ah[4], al[4];
            const int ab = aoff + kc * 16;
            ah[0] = *(const uint32_t*)&bufp[QB_AH + ab];
            ah[1] = *(const uint32_t*)&bufp[QB_AH + ab + 8 * PADW];
            ah[2] = *(const uint32_t*)&bufp[QB_AH + ab + 8];
            ah[3] = *(const uint32_t*)&bufp[QB_AH + ab + 8 * PADW + 8];
            al[0] = *(const uint32_t*)&bufp[QB_AL + ab];
            al[1] = *(const uint32_t*)&bufp[QB_AL + ab + 8 * PADW];
            al[2] = *(const uint32_t*)&bufp[QB_AL + ab + 8];
            al[3] = *(const uint32_t*)&bufp[QB_AL + ab + 8 * PADW + 8];
            #pragma unroll
            for (int j = 0; j < 8; j++) {
                const int bb = (j * 8 + g) * PADW + kc * 16 + 2 * tig;
                uint32_t bh[2], bl[2];
                bh[0] = *(const uint32_t*)&bufp[QB_BH + bb];
                bh[1] = *(const uint32_t*)&bufp[QB_BH + bb + 8];
                bl[0] = *(const uint32_t*)&bufp[QB_BL + bb];
                bl[1] = *(const uint32_t*)&bufp[QB_BL + bb + 8];
                mma16816(sacc[j], ah, bh);
                mma16816(sacc[j], al, bh);
                mma16816(sacc[j], ah, bl);
            }
        }
        __syncthreads();
    }

    // ---- epilogue: bias + qscale (Q folded with log2e), split, scatter ----
    const float qscale = (z == 0) ? 0.18033688011112042f : 1.0f;  // 0.125*log2(e)
    const int r0 = m0 + wid * 16 + g;
    const int r1 = r0 + 8;
    const int bb0 = r0 >> 11, nn0 = r0 & (NSEQ - 1);
    const int bb1 = r1 >> 11, nn1 = r1 & (NSEQ - 1);

    #pragma unroll
    for (int j = 0; j < 8; j++) {
        const int cg = n0 + j * 8 + 2 * tig;
        const int h = cg >> 6, d = cg & 63;
        const float b0 = bias[cg], b1 = bias[cg + 1];
        float v00 = (sacc[j][0] + b0) * qscale, v01 = (sacc[j][1] + b1) * qscale;
        float v10 = (sacc[j][2] + b0) * qscale, v11 = (sacc[j][3] + b1) * qscale;
        uint32_t hi0, lo0, hi1, lo1;
        split2(v00, v01, hi0, lo0);
        split2(v10, v11, hi1, lo1);

        if (z == 2) {
            size_t base0 = ((size_t)(bb0 * NH + h) * DDIM + d) * NSEQ + nn0;
            size_t base1 = ((size_t)(bb1 * NH + h) * DDIM + d) * NSEQ + nn1;
            g_Vth[base0]        = __ushort_as_bfloat16((unsigned short)(hi0 & 0xffff));
            g_Vth[base0 + NSEQ] = __ushort_as_bfloat16((unsigned short)(hi0 >> 16));
            g_Vtl[base0]        = __ushort_as_bfloat16((unsigned short)(lo0 & 0xffff));
            g_Vtl[base0 + NSEQ] = __ushort_as_bfloat16((unsigned short)(lo0 >> 16));
            g_Vth[base1]        = __ushort_as_bfloat16((unsigned short)(hi1 & 0xffff));
            g_Vth[base1 + NSEQ] = __ushort_as_bfloat16((unsigned short)(hi1 >> 16));
            g_Vtl[base1]        = __ushort_as_bfloat16((unsigned short)(lo1 & 0xffff));
            g_Vtl[base1 + NSEQ] = __ushort_as_bfloat16((unsigned short)(lo1 >> 16));
        } else {
            __nv_bfloat16* dh = (z == 0) ? g_Qh : g_Kh;
            __nv_bfloat16* dl = (z == 0) ? g_Ql : g_Kl;
            size_t i0 = ((size_t)(bb0 * NH + h) * NSEQ + nn0) * DDIM + d;
            size_t i1 = ((size_t)(bb1 * NH + h) * NSEQ + nn1) * DDIM + d;
            *(uint32_t*)&dh[i0] = hi0; *(uint32_t*)&dl[i0] = lo0;
            *(uint32_t*)&dh[i1] = hi1; *(uint32_t*)&dl[i1] = lo1;
        }
    }
}

// ---------------------------------------------------------------------------
// Kernel 2: flash attention, deferred-PV pipeline, triple-buffered cp.async.
// smem: 3 x (KH|KL|VH|VL), each array 64 x PADW bf16 -> 110,592 B / CTA.
// ---------------------------------------------------------------------------
#define E_KH 0
#define E_KL 4608
#define E_VH 9216
#define E_VL 13824
#define BUF_ELEMS 18432
#define BUF_BYTES 36864
#define ATTN_SMEM_BYTES (3 * BUF_BYTES)

__global__ void __launch_bounds__(256, 2)
attn_kernel()
{
    extern __shared__ __nv_bfloat16 sm[];

    const int tid  = threadIdx.x;
    const int wid  = tid >> 5;
    const int lane = tid & 31;
    const int g    = lane >> 2;
    const int tig  = lane & 3;
    const int bh   = blockIdx.x;
    const int q0   = blockIdx.y * BM;

    const size_t hb = (size_t)bh * NSEQ * DDIM;
    const __nv_bfloat16* __restrict__ gkh = g_Kh + hb;
    const __nv_bfloat16* __restrict__ gkl = g_Kl + hb;
    const __nv_bfloat16* __restrict__ gvh = g_Vth + hb;   // [d][n]
    const __nv_bfloat16* __restrict__ gvl = g_Vtl + hb;

    const uint32_t smb = smem_u32(sm);
    const int r0 = q0 + wid * 16 + g;
    const int r1 = r0 + 8;

    // ---- Q A-fragments: load once, straight from gmem ----
    uint32_t qfh[4][4], qfl[4][4];
    {
        const __nv_bfloat16* qh = g_Qh + hb;
        const __nv_bfloat16* ql = g_Ql + hb;
        #pragma unroll
        for (int kc = 0; kc < 4; kc++) {
            const int c = kc * 16 + 2 * tig;
            qfh[kc][0] = *(const uint32_t*)(qh + (size_t)r0 * DDIM + c);
            qfh[kc][1] = *(const uint32_t*)(qh + (size_t)r1 * DDIM + c);
            qfh[kc][2] = *(const uint32_t*)(qh + (size_t)r0 * DDIM + c + 8);
            qfh[kc][3] = *(const uint32_t*)(qh + (size_t)r1 * DDIM + c + 8);
            qfl[kc][0] = *(const uint32_t*)(ql + (size_t)r0 * DDIM + c);
            qfl[kc][1] = *(const uint32_t*)(ql + (size_t)r1 * DDIM + c);
            qfl[kc][2] = *(const uint32_t*)(ql + (size_t)r0 * DDIM + c + 8);
            qfl[kc][3] = *(const uint32_t*)(ql + (size_t)r1 * DDIM + c + 8);
        }
    }

    auto issue_kv = [&](int kt) {
        const int k0 = kt * BN;
        const uint32_t bufb = smb + (uint32_t)((kt % 3) * BUF_BYTES);
        #pragma unroll
        for (int f = tid; f < 512; f += 256) {
            const int r = f >> 3, c = (f & 7) << 3;
            const uint32_t ro = (uint32_t)(r * PADW + c) * 2;
            cp16(bufb + 2 * E_KH + ro, gkh + (size_t)(k0 + r) * DDIM + c);
            cp16(bufb + 2 * E_KL + ro, gkl + (size_t)(k0 + r) * DDIM + c);
            cp16(bufb + 2 * E_VH + ro, gvh + (size_t)r * NSEQ + k0 + c);
            cp16(bufb + 2 * E_VL + ro, gvl + (size_t)r * NSEQ + k0 + c);
        }
        CP_COMMIT();
    };

    issue_kv(0);
    issue_kv(1);

    float oacc[8][4];
    #pragma unroll
    for (int j = 0; j < 8; j++)
        #pragma unroll
        for (int t = 0; t < 4; t++) oacc[j][t] = 0.0f;
    float m0r = -3.0e38f, m1r = -3.0e38f, l0 = 0.0f, l1 = 0.0f;

    uint32_t pph[4][4], ppl[4][4];   // P fragments of previous tile

    for (int kt = 0; kt < NT; kt++) {
        const int k0 = kt * BN;
        CP_WAIT1();            // tile kt landed (only kt+1 may be pending)
        __syncthreads();       // visibility + all warps done with iter kt-1

        // ---- PV-MMA for PREVIOUS tile (pp frags, V(kt-1)) — issues first ----
        if (kt > 0) {
            const __nv_bfloat16* bufV = sm + ((kt + 2) % 3) * BUF_ELEMS;
            #pragma unroll
            for (int kc = 0; kc < 4; kc++) {
                #pragma unroll
                for (int j = 0; j < 8; j++) {
                    const int bb = (j * 8 + g) * PADW + kc * 16 + 2 * tig;
                    uint32_t bvh[2], bvl[2];
                    bvh[0] = *(const uint32_t*)&bufV[E_VH + bb];
                    bvh[1] = *(const uint32_t*)&bufV[E_VH + bb + 8];
                    bvl[0] = *(const uint32_t*)&bufV[E_VL + bb];
                    bvl[1] = *(const uint32_t*)&bufV[E_VL + bb + 8];
                    mma16816(oacc[j], pph[kc], bvh);
                    mma16816(oacc[j], ppl[kc], bvh);
                    mma16816(oacc[j], pph[kc], bvl);
                }
            }
        }

        // ---- S = Qh*Kh + Ql*Kh + Qh*Kl on tile kt ----
        const __nv_bfloat16* bufK = sm + (kt % 3) * BUF_ELEMS;
        float sacc[8][4];
        #pragma unroll
        for (int j = 0; j < 8; j++)
            #pragma unroll
            for (int t = 0; t < 4; t++) sacc[j][t] = 0.0f;

        #pragma unroll
        for (int kc = 0; kc < 4; kc++) {
            #pragma unroll
            for (int j = 0; j < 8; j++) {
                const int bb = (j * 8 + g) * PADW + kc * 16 + 2 * tig;
                uint32_t bkh[2], bkl[2];
                bkh[0] = *(const uint32_t*)&bufK[E_KH + bb];
                bkh[1] = *(const uint32_t*)&bufK[E_KH + bb + 8];
                bkl[0] = *(const uint32_t*)&bufK[E_KL + bb];
                bkl[1] = *(const uint32_t*)&bufK[E_KL + bb + 8];
                mma16816(sacc[j], qfh[kc], bkh);
                mma16816(sacc[j], qfl[kc], bkh);
                mma16816(sacc[j], qfh[kc], bkl);
            }
        }

        // ---- exclude-self mask ----
        #pragma unroll
        for (int j = 0; j < 8; j++) {
            const int cc = k0 + j * 8 + 2 * tig;
            if (cc == r0)     sacc[j][0] = -1.0e9f;
            if (cc + 1 == r0) sacc[j][1] = -1.0e9f;
            if (cc == r1)     sacc[j][2] = -1.0e9f;
            if (cc + 1 == r1) sacc[j][3] = -1.0e9f;
        }

        // ---- online softmax (base-2 domain; overlaps in-flight HMMAs) ----
        float mt0 = sacc[0][0], mt1 = sacc[0][2];
        #pragma unroll
        for (int j = 0; j < 8; j++) {
            mt0 = fmaxf(mt0, fmaxf(sacc[j][0], sacc[j][1]));
            mt1 = fmaxf(mt1, fmaxf(sacc[j][2], sacc[j][3]));
        }
        mt0 = fmaxf(mt0, __shfl_xor_sync(0xffffffffu, mt0, 1));
        mt0 = fmaxf(mt0, __shfl_xor_sync(0xffffffffu, mt0, 2));
        mt1 = fmaxf(mt1, __shfl_xor_sync(0xffffffffu, mt1, 1));
        mt1 = fmaxf(mt1, __shfl_xor_sync(0xffffffffu, mt1, 2));
        const float mn0 = fmaxf(m0r, mt0);
        const float mn1 = fmaxf(m1r, mt1);
        const float corr0 = ex2(m0r - mn0);
        const float corr1 = ex2(m1r - mn1);
        m0r = mn0; m1r = mn1;

        float rs0 = 0.0f, rs1 = 0.0f;
        #pragma unroll
        for (int j = 0; j < 8; j++) {
            sacc[j][0] = ex2(sacc[j][0] - mn0);
            sacc[j][1] = ex2(sacc[j][1] - mn0);
            sacc[j][2] = ex2(sacc[j][2] - mn1);
            sacc[j][3] = ex2(sacc[j][3] - mn1);
            rs0 += sacc[j][0] + sacc[j][1];
            rs1 += sacc[j][2] + sacc[j][3];
        }
        rs0 += __shfl_xor_sync(0xffffffffu, rs0, 1);
        rs0 += __shfl_xor_sync(0xffffffffu, rs0, 2);
        rs1 += __shfl_xor_sync(0xffffffffu, rs1, 1);
        rs1 += __shfl_xor_sync(0xffffffffu, rs1, 2);
        l0 = l0 * corr0 + rs0;
        l1 = l1 * corr1 + rs1;

        // ---- rescale O (waits on PV(kt-1) results) ----
        #pragma unroll
        for (int j = 0; j < 8; j++) {
            oacc[j][0] *= corr0; oacc[j][1] *= corr0;
            oacc[j][2] *= corr1; oacc[j][3] *= corr1;
        }

        // ---- split P -> bf16 hi/lo fragments for next iteration's PV ----
        #pragma unroll
        for (int kc = 0; kc < 4; kc++) {
            const int j0 = 2 * kc, j1 = 2 * kc + 1;
            split2(sacc[j0][0], sacc[j0][1], pph[kc][0], ppl[kc][0]);
            split2(sacc[j0][2], sacc[j0][3], pph[kc][1], ppl[kc][1]);
            split2(sacc[j1][0], sacc[j1][1], pph[kc][2], ppl[kc][2]);
            split2(sacc[j1][2], sacc[j1][3], pph[kc][3], ppl[kc][3]);
        }

        __syncthreads();       // all warps done reading V(kt-1) (buffer (kt+2)%3)
        if (kt + 2 < NT) issue_kv(kt + 2);
    }

    // ---- final PV for tile NT-1 ----
    {
        const __nv_bfloat16* bufV = sm + ((NT - 1) % 3) * BUF_ELEMS;
        #pragma unroll
        for (int kc = 0; kc < 4; kc++) {
            #pragma unroll
            for (int j = 0; j < 8; j++) {
                const int bb = (j * 8 + g) * PADW + kc * 16 + 2 * tig;
                uint32_t bvh[2], bvl[2];
                bvh[0] = *(const uint32_t*)&bufV[E_VH + bb];
                bvh[1] = *(const uint32_t*)&bufV[E_VH + bb + 8];
                bvl[0] = *(const uint32_t*)&bufV[E_VL + bb];
                bvl[1] = *(const uint32_t*)&bufV[E_VL + bb + 8];
                mma16816(oacc[j], pph[kc], bvh);
                mma16816(oacc[j], ppl[kc], bvh);
                mma16816(oacc[j], pph[kc], bvl);
            }
        }
    }

    // ---- epilogue: ctx split-bf16 [b][n][h*64+d] ----
    const int bb = bh >> 3, h = bh & 7;
    const float inv0 = 1.0f / l0;
    const float inv1 = 1.0f / l1;
    size_t base0 = ((size_t)bb * NSEQ + r0) * HD + h * DDIM;
    size_t base1 = ((size_t)bb * NSEQ + r1) * HD + h * DDIM;
    #pragma unroll
    for (int j = 0; j < 8; j++) {
        const int c = j * 8 + 2 * tig;
        uint32_t hi, lo;
        split2(oacc[j][0] * inv0, oacc[j][1] * inv0, hi, lo);
        *(uint32_t*)&g_Ch[base0 + c] = hi;
        *(uint32_t*)&g_Cl[base0 + c] = lo;
        split2(oacc[j][2] * inv1, oacc[j][3] * inv1, hi, lo);
        *(uint32_t*)&g_Ch[base1 + c] = hi;
        *(uint32_t*)&g_Cl[base1 + c] = lo;
    }
}

// ---------------------------------------------------------------------------
// Kernel 3: out = ctx @ Wo. CTA 64x64 (4 warps), cp.async double-buffered.
// ---------------------------------------------------------------------------
#define PB_AH 0
#define PB_AL 4608
#define PB_BH 9216
#define PB_BL 13824
#define PB_ELEMS 18432
#define PB_BYTES 36864
#define PJ_SMEM_BYTES (2 * PB_BYTES)

__global__ void __launch_bounds__(128)
proj_kernel(float* __restrict__ out)
{
    extern __shared__ __nv_bfloat16 sm[];

    const int tid  = threadIdx.x;
    const int wid  = tid >> 5;
    const int lane = tid & 31;
    const int g    = lane >> 2;
    const int tig  = lane & 3;
    const int m0   = blockIdx.x * 64;

    const uint32_t smb = smem_u32(sm);

    auto issue = [&](int c) {
        const int k0 = c * 64;
        const uint32_t bufb = smb + (uint32_t)((c & 1) * PB_BYTES);
        for (int f = tid; f < 512; f += 128) {
            const int r = f >> 3, cc = (f & 7) << 3;
            const uint32_t ro = (uint32_t)(r * PADW + cc) * 2;
            cp16(bufb + 2 * PB_AH + ro, g_Ch + (size_t)(m0 + r) * HD + k0 + cc);
            cp16(bufb + 2 * PB_AL + ro, g_Cl + (size_t)(m0 + r) * HD + k0 + cc);
            cp16(bufb + 2 * PB_BH + ro, g_Woth + (size_t)r * HD + k0 + cc);
            cp16(bufb + 2 * PB_BL + ro, g_Wotl + (size_t)r * HD + k0 + cc);
        }
        CP_COMMIT();
    };

    issue(0);

    float sacc[8][4];
    #pragma unroll
    for (int j = 0; j < 8; j++)
        #pragma unroll
        for (int t = 0; t < 4; t++) sacc[j][t] = 0.0f;

    const int aoff = (wid * 16 + g) * PADW + 2 * tig;

    for (int c0 = 0; c0 < 8; c0++) {
        CP_WAIT0();
        __syncthreads();
        if (c0 + 1 < 8) issue(c0 + 1);

        const __nv_bfloat16* bufp = sm + (c0 & 1) * PB_ELEMS;

        #pragma unroll
        for (int kc = 0; kc < 4; kc++) {
            uint32_t ah[4], al[4];
            const int ab = aoff + kc * 16;
            ah[0] = *(const uint32_t*)&bufp[PB_AH + ab];
            ah[1] = *(const uint32_t*)&bufp[PB_AH + ab + 8 * PADW];
            ah[2] = *(const uint32_t*)&bufp[PB_AH + ab + 8];
            ah[3] = *(const uint32_t*)&bufp[PB_AH + ab + 8 * PADW + 8];
            al[0] = *(const uint32_t*)&bufp[PB_AL + ab];
            al[1] = *(const uint32_t*)&bufp[PB_AL + ab + 8 * PADW];
            al[2] = *(const uint32_t*)&bufp[PB_AL + ab + 8];
            al[3] = *(const uint32_t*)&bufp[PB_AL + ab + 8 * PADW + 8];
            #pragma unroll
            for (int j = 0; j < 8; j++) {
                const int bb = (j * 8 + g) * PADW + kc * 16 + 2 * tig;
                uint32_t bh[2], bl[2];
                bh[0] = *(const uint32_t*)&bufp[PB_BH + bb];
                bh[1] = *(const uint32_t*)&bufp[PB_BH + bb + 8];
                bl[0] = *(const uint32_t*)&bufp[PB_BL + bb];
                bl[1] = *(const uint32_t*)&bufp[PB_BL + bb + 8];
                mma16816(sacc[j], ah, bh);
                mma16816(sacc[j], al, bh);
                mma16816(sacc[j], ah, bl);
            }
        }
        __syncthreads();
    }

    const int r0 = m0 + wid * 16 + g;
    const int r1 = r0 + 8;
    #pragma unroll
    for (int j = 0; j < 8; j++) {
        const int c = j * 8 + 2 * tig;
        *(float2*)(out + (size_t)r0 * DDIM + c) = make_float2(sacc[j][0], sacc[j][1]);
        *(float2*)(out + (size_t)r1 * DDIM + c) = make_float2(sacc[j][2], sacc[j][3]);
    }
}

// ---------------------------------------------------------------------------
extern "C" void kernel_launch(void* const* d_in, const int* in_sizes, int n_in,
                              void* d_out, int out_size)
{
    const float* msg = (const float*)d_in[0];
    const float* Wq  = (const float*)d_in[1];
    const float* bq  = (const float*)d_in[2];
    const float* Wk  = (const float*)d_in[3];
    const float* bk  = (const float*)d_in[4];
    const float* Wv  = (const float*)d_in[5];
    const float* bv  = (const float*)d_in[6];
    const float* Wo  = (const float*)d_in[7];
    float* out = (float*)d_out;

    cudaFuncSetAttribute(qkv_kernel,  cudaFuncAttributeMaxDynamicSharedMemorySize, QK_SMEM_BYTES);
    cudaFuncSetAttribute(attn_kernel, cudaFuncAttributeMaxDynamicSharedMemorySize, ATTN_SMEM_BYTES);
    cudaFuncSetAttribute(proj_kernel, cudaFuncAttributeMaxDynamicSharedMemorySize, PJ_SMEM_BYTES);

    conv_kernel<<<2048, 256>>>(msg, Wq, Wk, Wv, Wo);
    qkv_kernel<<<dim3(128, 8, 3), 256, QK_SMEM_BYTES>>>(bq, bk, bv);
    attn_kernel<<<dim3(NB * NH, NSEQ / BM), 256, ATTN_SMEM_BYTES>>>();
    proj_kernel<<<dim3(256, 1, 1), 128, PJ_SMEM_BYTES>>>(out);
}